// round 4
// baseline (speedup 1.0000x reference)
#include <cuda_runtime.h>
#include <cuda_bf16.h>
#include <cstdint>

#define S_LEN 8192
#define HD 64
#define NHEADS 8
#define WW 512
#define KSPLIT 2
#define QB 128
#define NQB (S_LEN/QB)            /* 64  */
#define NKT ((S_LEN/KSPLIT)/64)   /* 64  key tiles of 64 */
#define CEXP 0.1803368801111204f  /* 0.125 * log2(e) */

static __device__ float g_wsum[HD * WW];
static __device__ float g_Opart[KSPLIT][S_LEN * HD];
static __device__ float g_lpart[KSPLIT][S_LEN];

// ---------------- helpers ----------------
__device__ __forceinline__ uint32_t smem_u32(const void* p) {
    uint32_t a;
    asm("{ .reg .u64 t; cvta.to.shared.u64 t, %1; cvt.u32.u64 %0, t; }" : "=r"(a) : "l"(p));
    return a;
}
__device__ __forceinline__ void ldsm4(uint32_t* r, uint32_t a) {
    asm volatile("ldmatrix.sync.aligned.m8n8.x4.shared.b16 {%0,%1,%2,%3}, [%4];"
                 : "=r"(r[0]), "=r"(r[1]), "=r"(r[2]), "=r"(r[3]) : "r"(a));
}
__device__ __forceinline__ void ldsm4t(uint32_t* r, uint32_t a) {
    asm volatile("ldmatrix.sync.aligned.m8n8.x4.trans.shared.b16 {%0,%1,%2,%3}, [%4];"
                 : "=r"(r[0]), "=r"(r[1]), "=r"(r[2]), "=r"(r[3]) : "r"(a));
}
__device__ __forceinline__ void mma16816(float* d, const uint32_t* a, uint32_t b0, uint32_t b1) {
    asm volatile(
        "mma.sync.aligned.m16n8k16.row.col.f32.bf16.bf16.f32 "
        "{%0,%1,%2,%3}, {%4,%5,%6,%7}, {%8,%9}, {%0,%1,%2,%3};"
        : "+f"(d[0]), "+f"(d[1]), "+f"(d[2]), "+f"(d[3])
        : "r"(a[0]), "r"(a[1]), "r"(a[2]), "r"(a[3]), "r"(b0), "r"(b1));
}
__device__ __forceinline__ uint32_t bpack(float a, float b) {
    uint32_t r;
    asm("cvt.rn.bf16x2.f32 %0, %1, %2;" : "=r"(r) : "f"(b), "f"(a));
    return r;
}
__device__ __forceinline__ void packpair(float a, float b, uint32_t& hi, uint32_t& lo) {
    hi = bpack(a, b);
    float fa = __uint_as_float(hi << 16);
    float fb = __uint_as_float(hi & 0xFFFF0000u);
    lo = bpack(a - fa, b - fb);
}
__device__ __forceinline__ float ex2f(float x) {
    float y; asm("ex2.approx.f32 %0, %1;" : "=f"(y) : "f"(x)); return y;
}

// stage 16 fp32 (dims 16*qd..16*qd+15 of row `key`) into hi/lo bf16 tiles
__device__ __forceinline__ void stage16(unsigned char* baseH, unsigned char* baseL,
                                        int key, int qd, const float4* f) {
    float fv[16];
#pragma unroll
    for (int i = 0; i < 4; ++i) {
        fv[4*i] = f[i].x; fv[4*i+1] = f[i].y; fv[4*i+2] = f[i].z; fv[4*i+3] = f[i].w;
    }
    uint32_t hh[8], ll[8];
#pragma unroll
    for (int p = 0; p < 8; ++p) packpair(fv[2*p], fv[2*p+1], hh[p], ll[p]);
    const int kx = key & 7;
    const int off0 = key * 128 + (((2*qd)   ^ kx) << 4);
    const int off1 = key * 128 + (((2*qd+1) ^ kx) << 4);
    *(uint4*)(baseH + off0) = make_uint4(hh[0], hh[1], hh[2], hh[3]);
    *(uint4*)(baseH + off1) = make_uint4(hh[4], hh[5], hh[6], hh[7]);
    *(uint4*)(baseL + off0) = make_uint4(ll[0], ll[1], ll[2], ll[3]);
    *(uint4*)(baseL + off1) = make_uint4(ll[4], ll[5], ll[6], ll[7]);
}

// ---------------------------------------------------------------------------
// Kernel 1: W_sum reduce
// ---------------------------------------------------------------------------
__global__ void wsum_kernel(const float* __restrict__ w_o) {
    int idx = blockIdx.x * blockDim.x + threadIdx.x;
    int d = idx >> 9;
    int c = idx & 511;
    float s = 0.f;
#pragma unroll
    for (int h = 0; h < NHEADS; ++h)
        s += w_o[(h * HD + d) * WW + c];
    g_wsum[idx] = s;
}

// ---------------------------------------------------------------------------
// Kernel 2: mma.sync flash attention, double-buffered smem.
// Grid = 128 (64 q-blocks x 2 key splits), 256 threads.
// Dynamic smem 64KB: buf b at sm + b*32768; within buf: KH@0 KL@8K VH@16K VL@24K.
// ---------------------------------------------------------------------------
__global__ __launch_bounds__(256, 1)
void attn_mma(const float* __restrict__ q, const float* __restrict__ k,
              const float* __restrict__ v) {
    extern __shared__ __align__(1024) unsigned char sm[];

    const int tid = threadIdx.x;
    const int w   = tid >> 5;
    const int l   = tid & 31;
    const int qb    = blockIdx.x & (NQB - 1);
    const int split = blockIdx.x >> 6;
    const int kvBase = split * (S_LEN / KSPLIT);

    // ---- Q staging (uses buf0 area, freed before mainloop) ----
    {
        const int row = tid >> 1, hf = tid & 1;
        const float4* q4 = reinterpret_cast<const float4*>(
            q + (size_t)(qb * QB + row) * HD + hf * 32);
#pragma unroll
        for (int i = 0; i < 2; ++i) {
            float4 f[4];
#pragma unroll
            for (int j = 0; j < 4; ++j) f[j] = q4[i * 4 + j];
            stage16(sm, sm + 16384, row, 2 * hf + i, f);
        }
    }
    __syncthreads();

    // ---- persistent Q fragments ----
    uint32_t Qh[4][4], Ql[4][4];
    {
        const int r = l & 7, sel = (l >> 3) & 1, hi8 = l >> 4;
        const int qrow = w * 16 + r + sel * 8;
#pragma unroll
        for (int kc = 0; kc < 4; ++kc) {
            const int c = 2 * kc + hi8;
            const uint32_t a = smem_u32(sm) + qrow * 128 + ((c ^ (qrow & 7)) << 4);
            ldsm4(Qh[kc], a);
            ldsm4(Ql[kc], a + 16384);
        }
    }
    __syncthreads();   // Q staging area about to be reused

    float O[8][4];
#pragma unroll
    for (int n = 0; n < 8; ++n)
#pragma unroll
        for (int j = 0; j < 4; ++j) O[n][j] = 0.f;
    float lacc0 = 0.f, lacc1 = 0.f;

    const int key = tid >> 2, qd = tid & 3;
    const float4* kg = reinterpret_cast<const float4*>(k + (size_t)(kvBase + key) * HD) + qd * 4;
    const float4* vg = reinterpret_cast<const float4*>(v + (size_t)(kvBase + key) * HD) + qd * 4;
    const int strideF4 = 64 * HD / 4;

    float4 kReg[4], vReg[4];
#pragma unroll
    for (int i = 0; i < 4; ++i) { kReg[i] = kg[i]; vReg[i] = vg[i]; }
    // stage tile 0 into buf0
    stage16(sm,         sm + 8192,  key, qd, kReg);
    stage16(sm + 16384, sm + 24576, key, qd, vReg);
    // prefetch tile 1
#pragma unroll
    for (int i = 0; i < 4; ++i) { kReg[i] = kg[strideF4 + i]; vReg[i] = vg[strideF4 + i]; }
    __syncthreads();

    const uint32_t smBase = smem_u32(sm);
    const int r = l & 7;

    for (int kb = 0; kb < NKT; ++kb) {
        // ---- stage tile kb+1 into the other buffer (off critical path) ----
        if (kb + 1 < NKT) {
            unsigned char* nb = sm + (((kb + 1) & 1) << 15);
            stage16(nb,         nb + 8192,  key, qd, kReg);
            stage16(nb + 16384, nb + 24576, key, qd, vReg);
        }
        // ---- prefetch tile kb+2 ----
        if (kb + 2 < NKT) {
#pragma unroll
            for (int i = 0; i < 4; ++i) {
                kReg[i] = kg[(kb + 2) * strideF4 + i];
                vReg[i] = vg[(kb + 2) * strideF4 + i];
            }
        }

        const uint32_t uKH = smBase + ((kb & 1) << 15);
        const uint32_t uVH = uKH + 16384;

        // ---- S = Q K^T (3-pass) ----
        float sD[8][4];
#pragma unroll
        for (int n = 0; n < 8; ++n)
#pragma unroll
            for (int j = 0; j < 4; ++j) sD[n][j] = 0.f;

#pragma unroll
        for (int np = 0; np < 4; ++np) {
#pragma unroll
            for (int kc = 0; kc < 4; ++kc) {
                const int kk = 16 * np + (l >> 4) * 8 + r;
                const int c  = 2 * kc + ((l >> 3) & 1);
                const uint32_t a = uKH + kk * 128 + ((c ^ (kk & 7)) << 4);
                uint32_t kh[4], kl_[4];
                ldsm4(kh, a);
                ldsm4(kl_, a + 8192);
                mma16816(sD[2*np],   Qh[kc], kh[0],  kh[1]);
                mma16816(sD[2*np+1], Qh[kc], kh[2],  kh[3]);
                mma16816(sD[2*np],   Qh[kc], kl_[0], kl_[1]);
                mma16816(sD[2*np+1], Qh[kc], kl_[2], kl_[3]);
                mma16816(sD[2*np],   Ql[kc], kh[0],  kh[1]);
                mma16816(sD[2*np+1], Ql[kc], kh[2],  kh[3]);
            }
        }

        // ---- softmax: P = exp(S/8) in registers ----
        uint32_t Ph[8][2], Pl[8][2];
#pragma unroll
        for (int n = 0; n < 8; ++n) {
            float e0 = ex2f(sD[n][0] * CEXP);
            float e1 = ex2f(sD[n][1] * CEXP);
            float e2 = ex2f(sD[n][2] * CEXP);
            float e3 = ex2f(sD[n][3] * CEXP);
            lacc0 += e0 + e1;
            lacc1 += e2 + e3;
            packpair(e0, e1, Ph[n][0], Pl[n][0]);
            packpair(e2, e3, Ph[n][1], Pl[n][1]);
        }

        // ---- O += P V (3-pass) ----
#pragma unroll
        for (int np = 0; np < 4; ++np) {
#pragma unroll
            for (int kcv = 0; kcv < 4; ++kcv) {
                const int kk = 16 * kcv + ((l >> 3) & 1) * 8 + r;
                const int c  = 2 * np + (l >> 4);
                const uint32_t a = uVH + kk * 128 + ((c ^ (kk & 7)) << 4);
                uint32_t vh[4], vl_[4];
                ldsm4t(vh, a);
                ldsm4t(vl_, a + 8192);
                uint32_t Ah[4] = {Ph[2*kcv][0], Ph[2*kcv][1], Ph[2*kcv+1][0], Ph[2*kcv+1][1]};
                uint32_t Al[4] = {Pl[2*kcv][0], Pl[2*kcv][1], Pl[2*kcv+1][0], Pl[2*kcv+1][1]};
                mma16816(O[2*np],   Ah, vh[0],  vh[1]);
                mma16816(O[2*np+1], Ah, vh[2],  vh[3]);
                mma16816(O[2*np],   Ah, vl_[0], vl_[1]);
                mma16816(O[2*np+1], Ah, vl_[2], vl_[3]);
                mma16816(O[2*np],   Al, vh[0],  vh[1]);
                mma16816(O[2*np+1], Al, vh[2],  vh[3]);
            }
        }
        __syncthreads();   // cur fully consumed; nxt staging complete
    }

    // ---- write partial O ----
    {
        const int row0 = qb * QB + w * 16 + (l >> 2);
        const int t    = l & 3;
        float* op = g_Opart[split];
#pragma unroll
        for (int n = 0; n < 8; ++n) {
            *reinterpret_cast<float2*>(op + (size_t)row0 * HD + 8 * n + 2 * t) =
                make_float2(O[n][0], O[n][1]);
            *reinterpret_cast<float2*>(op + (size_t)(row0 + 8) * HD + 8 * n + 2 * t) =
                make_float2(O[n][2], O[n][3]);
        }
    }
    lacc0 += __shfl_xor_sync(0xffffffffu, lacc0, 1);
    lacc0 += __shfl_xor_sync(0xffffffffu, lacc0, 2);
    lacc1 += __shfl_xor_sync(0xffffffffu, lacc1, 1);
    lacc1 += __shfl_xor_sync(0xffffffffu, lacc1, 2);
    if ((l & 3) == 0) {
        const int row0 = qb * QB + w * 16 + (l >> 2);
        g_lpart[split][row0]     = lacc0;
        g_lpart[split][row0 + 8] = lacc1;
    }
}

// ---------------------------------------------------------------------------
// Kernel 3: fused combine + output GEMM.
// out[64x64 tile] = ((O0+O1) * invl) @ W_sum   (64x64 tiles, 4x4 per thread)
// ---------------------------------------------------------------------------
__device__ __forceinline__ int swz_w(int kk, int j) {
    return kk * 64 + ((((j >> 2) ^ ((kk >> 2) & 15)) << 2) | (j & 3));
}

__global__ __launch_bounds__(256, 2) void out_gemm(float* __restrict__ out) {
    __shared__ float sHT[4096];
    __shared__ float sW[4096];
    __shared__ float sInv[64];

    const int tid = threadIdx.x;
    const int tx = tid & 15;
    const int ty = tid >> 4;
    const int i0 = ty * 4;
    const int mBase = blockIdx.x * 64;
    const int nBase = blockIdx.y * 64;

    if (tid < 64)
        sInv[tid] = 1.0f / (g_lpart[0][mBase + tid] + g_lpart[1][mBase + tid]);
    __syncthreads();

    const float4* o0 = reinterpret_cast<const float4*>(g_Opart[0] + (size_t)mBase * HD);
    const float4* o1 = reinterpret_cast<const float4*>(g_Opart[1] + (size_t)mBase * HD);
    const float4* w4 = reinterpret_cast<const float4*>(g_wsum);
#pragma unroll
    for (int it = 0; it < 4; ++it) {
        int idx = tid + it * 256;
        int c4  = idx & 15;
        int rowi = idx >> 4;
        float4 a = o0[rowi * 16 + c4];
        float4 b = o1[rowi * 16 + c4];
        float inv = sInv[rowi];
        float vv[4] = {(a.x + b.x) * inv, (a.y + b.y) * inv,
                       (a.z + b.z) * inv, (a.w + b.w) * inv};
#pragma unroll
        for (int e = 0; e < 4; ++e)
            sHT[swz_w(c4 * 4 + e, rowi)] = vv[e];
        float4 wv = w4[rowi * 128 + (nBase >> 2) + c4];
        *reinterpret_cast<float4*>(&sW[rowi * 64 + c4 * 4]) = wv;
    }
    __syncthreads();

    float o[4][4];
#pragma unroll
    for (int rr = 0; rr < 4; ++rr)
#pragma unroll
        for (int cc = 0; cc < 4; ++cc) o[rr][cc] = 0.f;

#pragma unroll 8
    for (int kk = 0; kk < 64; ++kk) {
        int sw = (kk >> 2) & 15;
        float4 a = *reinterpret_cast<const float4*>(&sHT[kk * 64 + ((ty ^ sw) << 2)]);
        float4 b = *reinterpret_cast<const float4*>(&sW[kk * 64 + tx * 4]);
        float av[4] = {a.x, a.y, a.z, a.w};
        float bv[4] = {b.x, b.y, b.z, b.w};
#pragma unroll
        for (int rr = 0; rr < 4; ++rr)
#pragma unroll
            for (int cc = 0; cc < 4; ++cc)
                o[rr][cc] = fmaf(av[rr], bv[cc], o[rr][cc]);
    }

#pragma unroll
    for (int rr = 0; rr < 4; ++rr)
        *reinterpret_cast<float4*>(&out[(size_t)(mBase + i0 + rr) * WW + nBase + tx * 4]) =
            make_float4(o[rr][0], o[rr][1], o[rr][2], o[rr][3]);
}

// ---------------------------------------------------------------------------
extern "C" void kernel_launch(void* const* d_in, const int* in_sizes, int n_in,
                              void* d_out, int out_size) {
    const float* q   = (const float*)d_in[0];
    const float* k   = (const float*)d_in[1];
    const float* v   = (const float*)d_in[2];
    const float* w_o = (const float*)d_in[3];
    float* out = (float*)d_out;

    cudaFuncSetAttribute(attn_mma, cudaFuncAttributeMaxDynamicSharedMemorySize, 65536);

    wsum_kernel<<<64, 512>>>(w_o);
    attn_mma<<<NQB * KSPLIT, 256, 65536>>>(q, k, v);
    out_gemm<<<dim3(S_LEN / 64, WW / 64), 256>>>(out);
}

// round 5
// speedup vs baseline: 1.0766x; 1.0766x over previous
#include <cuda_runtime.h>
#include <cuda_bf16.h>
#include <cstdint>

#define S_LEN 8192
#define HD 64
#define NHEADS 8
#define WW 512
#define KSPLIT 2
#define QB 128
#define NQB (S_LEN/QB)            /* 64 */
#define NKT ((S_LEN/KSPLIT)/64)   /* 64 key tiles of 64 */
#define CEXP 0.1803368801111204f  /* 0.125 * log2(e) */

static __device__ float g_wsum[HD * WW];
static __device__ float g_Opart[KSPLIT][S_LEN * HD];
static __device__ float g_lpart[KSPLIT][S_LEN];
// pre-converted bf16 hi/lo operands, [row][dim] linear
static __device__ __align__(16) __nv_bfloat16 g_qh[S_LEN * HD], g_ql[S_LEN * HD];
static __device__ __align__(16) __nv_bfloat16 g_kh[S_LEN * HD], g_kl[S_LEN * HD];
static __device__ __align__(16) __nv_bfloat16 g_vh[S_LEN * HD], g_vl[S_LEN * HD];

// ---------------- helpers ----------------
__device__ __forceinline__ uint32_t smem_u32(const void* p) {
    uint32_t a;
    asm("{ .reg .u64 t; cvta.to.shared.u64 t, %1; cvt.u32.u64 %0, t; }" : "=r"(a) : "l"(p));
    return a;
}
__device__ __forceinline__ void ldsm4(uint32_t* r, uint32_t a) {
    asm volatile("ldmatrix.sync.aligned.m8n8.x4.shared.b16 {%0,%1,%2,%3}, [%4];"
                 : "=r"(r[0]), "=r"(r[1]), "=r"(r[2]), "=r"(r[3]) : "r"(a));
}
__device__ __forceinline__ void ldsm4t(uint32_t* r, uint32_t a) {
    asm volatile("ldmatrix.sync.aligned.m8n8.x4.trans.shared.b16 {%0,%1,%2,%3}, [%4];"
                 : "=r"(r[0]), "=r"(r[1]), "=r"(r[2]), "=r"(r[3]) : "r"(a));
}
__device__ __forceinline__ void mma16816(float* d, const uint32_t* a, uint32_t b0, uint32_t b1) {
    asm volatile(
        "mma.sync.aligned.m16n8k16.row.col.f32.bf16.bf16.f32 "
        "{%0,%1,%2,%3}, {%4,%5,%6,%7}, {%8,%9}, {%0,%1,%2,%3};"
        : "+f"(d[0]), "+f"(d[1]), "+f"(d[2]), "+f"(d[3])
        : "r"(a[0]), "r"(a[1]), "r"(a[2]), "r"(a[3]), "r"(b0), "r"(b1));
}
__device__ __forceinline__ uint32_t bpack(float a, float b) {
    uint32_t r;
    asm("cvt.rn.bf16x2.f32 %0, %1, %2;" : "=r"(r) : "f"(b), "f"(a));
    return r;
}
__device__ __forceinline__ void packpair(float a, float b, uint32_t& hi, uint32_t& lo) {
    hi = bpack(a, b);
    float fa = __uint_as_float(hi << 16);
    float fb = __uint_as_float(hi & 0xFFFF0000u);
    lo = bpack(a - fa, b - fb);
}
__device__ __forceinline__ float ex2f(float x) {
    float y; asm("ex2.approx.f32 %0, %1;" : "=f"(y) : "f"(x)); return y;
}
#define CP_ASYNC16(dst, src) \
    asm volatile("cp.async.cg.shared.global [%0], [%1], 16;" :: "r"(dst), "l"(src))
#define CP_COMMIT() asm volatile("cp.async.commit_group;" ::: "memory")
#define CP_WAIT(n)  asm volatile("cp.async.wait_group %0;" :: "n"(n) : "memory")

// ---------------------------------------------------------------------------
// Kernel 0: convert q/k/v fp32 -> bf16 hi/lo (linear layout)
// 32768 threads, each handles 16 consecutive elements of each tensor.
// ---------------------------------------------------------------------------
__device__ __forceinline__ void cvt16(const float4* s, __nv_bfloat16* h, __nv_bfloat16* lo) {
    float fv[16];
#pragma unroll
    for (int i = 0; i < 4; ++i) {
        float4 t = s[i];
        fv[4*i] = t.x; fv[4*i+1] = t.y; fv[4*i+2] = t.z; fv[4*i+3] = t.w;
    }
    uint32_t hh[8], ll[8];
#pragma unroll
    for (int p = 0; p < 8; ++p) packpair(fv[2*p], fv[2*p+1], hh[p], ll[p]);
    reinterpret_cast<uint4*>(h)[0]  = make_uint4(hh[0], hh[1], hh[2], hh[3]);
    reinterpret_cast<uint4*>(h)[1]  = make_uint4(hh[4], hh[5], hh[6], hh[7]);
    reinterpret_cast<uint4*>(lo)[0] = make_uint4(ll[0], ll[1], ll[2], ll[3]);
    reinterpret_cast<uint4*>(lo)[1] = make_uint4(ll[4], ll[5], ll[6], ll[7]);
}

__global__ void convert_kernel(const float* __restrict__ q, const float* __restrict__ k,
                               const float* __restrict__ v) {
    int t = blockIdx.x * blockDim.x + threadIdx.x;   // 0..32767
    int off = t * 16;
    cvt16(reinterpret_cast<const float4*>(q + off), g_qh + off, g_ql + off);
    cvt16(reinterpret_cast<const float4*>(k + off), g_kh + off, g_kl + off);
    cvt16(reinterpret_cast<const float4*>(v + off), g_vh + off, g_vl + off);
}

// ---------------------------------------------------------------------------
// Kernel 1: W_sum reduce
// ---------------------------------------------------------------------------
__global__ void wsum_kernel(const float* __restrict__ w_o) {
    int idx = blockIdx.x * blockDim.x + threadIdx.x;
    int d = idx >> 9;
    int c = idx & 511;
    float s = 0.f;
#pragma unroll
    for (int h = 0; h < NHEADS; ++h)
        s += w_o[(h * HD + d) * WW + c];
    g_wsum[idx] = s;
}

// ---------------------------------------------------------------------------
// Kernel 2: flash attention, 128 threads (4 warps x 32 rows), cp.async staging,
// triple-buffered K/V. Smem: Q hi/lo @0 (32KB); bufs @32768 + b*32768,
// each buf: KH@0 KL@8192 VH@16384 VL@24576.
// ---------------------------------------------------------------------------
struct TileSrc { const __nv_bfloat16* p[4]; };

__device__ __forceinline__ void issue_tile(uint32_t bufBase, int kvRow0, int tid) {
    const int key = tid >> 1, sel = tid & 1;
    const size_t gOff = (size_t)(kvRow0 + key) * HD;
    const __nv_bfloat16* srcs[4] = {g_kh, g_kl, g_vh, g_vl};
#pragma unroll
    for (int a = 0; a < 4; ++a) {
        const __nv_bfloat16* src = srcs[a] + gOff;
        const uint32_t dstRow = bufBase + a * 8192 + key * 128;
#pragma unroll
        for (int i = 0; i < 4; ++i) {
            const int ch = sel * 4 + i;
            CP_ASYNC16(dstRow + ((ch ^ (key & 7)) << 4), src + ch * 8);
        }
    }
}

__global__ __launch_bounds__(128, 1)
void attn_mma(const float* __restrict__ q, const float* __restrict__ k,
              const float* __restrict__ v) {
    extern __shared__ __align__(1024) unsigned char sm[];
    const int tid = threadIdx.x;
    const int w   = tid >> 5;
    const int l   = tid & 31;
    const int qb    = blockIdx.x & (NQB - 1);
    const int split = blockIdx.x >> 6;
    const int kvBase = split * (S_LEN / KSPLIT);
    const uint32_t smBase = smem_u32(sm);

    // ---- prologue: Q hi/lo via cp.async ----
    {
        const int row = tid;
        const uint32_t dstRow = smBase + row * 128;
        const size_t gOff = (size_t)(qb * QB + row) * HD;
#pragma unroll
        for (int i = 0; i < 8; ++i)
            CP_ASYNC16(dstRow + ((i ^ (row & 7)) << 4), g_qh + gOff + i * 8);
#pragma unroll
        for (int i = 0; i < 8; ++i)
            CP_ASYNC16(dstRow + 16384 + ((i ^ (row & 7)) << 4), g_ql + gOff + i * 8);
        CP_COMMIT();
    }
    issue_tile(smBase + 32768, kvBase, tid);          CP_COMMIT();
    issue_tile(smBase + 65536, kvBase + 64, tid);     CP_COMMIT();
    CP_WAIT(2);
    __syncthreads();

    // ---- persistent Q fragments: 2 M-frags of 16 rows per warp ----
    uint32_t Qh[2][4][4], Ql[2][4][4];
    {
        const int rr = (l & 7) + ((l >> 3) & 1) * 8, hi8 = l >> 4;
#pragma unroll
        for (int f = 0; f < 2; ++f) {
            const int qrow = w * 32 + f * 16 + rr;
#pragma unroll
            for (int kc = 0; kc < 4; ++kc) {
                const int c = 2 * kc + hi8;
                const uint32_t a = smBase + qrow * 128 + ((c ^ (qrow & 7)) << 4);
                ldsm4(Qh[f][kc], a);
                ldsm4(Ql[f][kc], a + 16384);
            }
        }
    }

    float O[2][8][4];
#pragma unroll
    for (int f = 0; f < 2; ++f)
#pragma unroll
        for (int n = 0; n < 8; ++n)
#pragma unroll
            for (int j = 0; j < 4; ++j) O[f][n][j] = 0.f;
    float lacc[2][2] = {{0.f, 0.f}, {0.f, 0.f}};

    for (int kb = 0; kb < NKT; ++kb) {
        CP_WAIT(1);          // tile kb resident; kb+1 in flight
        __syncthreads();     // all warps see data; buf (kb+2)%3 fully consumed
        if (kb + 2 < NKT)
            issue_tile(smBase + 32768 + ((kb + 2) % 3) * 32768,
                       kvBase + (kb + 2) * 64, tid);
        CP_COMMIT();         // empty group OK on tail iterations

        const uint32_t uKH = smBase + 32768 + (kb % 3) * 32768;
        const uint32_t uVH = uKH + 16384;

        // ---- S = Q K^T (3-pass split bf16), both M-frags share B loads ----
        float sD[2][8][4];
#pragma unroll
        for (int f = 0; f < 2; ++f)
#pragma unroll
            for (int n = 0; n < 8; ++n)
#pragma unroll
                for (int j = 0; j < 4; ++j) sD[f][n][j] = 0.f;

        const int rS = (l >> 4) * 8 + (l & 7);
        const int cSo = (l >> 3) & 1;
#pragma unroll
        for (int np = 0; np < 4; ++np) {
#pragma unroll
            for (int kc = 0; kc < 4; ++kc) {
                const int kk = 16 * np + rS;
                const int c  = 2 * kc + cSo;
                const uint32_t a = uKH + kk * 128 + ((c ^ (kk & 7)) << 4);
                uint32_t kh[4], kl_[4];
                ldsm4(kh, a);
                ldsm4(kl_, a + 8192);
#pragma unroll
                for (int f = 0; f < 2; ++f) {
                    mma16816(sD[f][2*np],   Qh[f][kc], kh[0],  kh[1]);
                    mma16816(sD[f][2*np+1], Qh[f][kc], kh[2],  kh[3]);
                    mma16816(sD[f][2*np],   Qh[f][kc], kl_[0], kl_[1]);
                    mma16816(sD[f][2*np+1], Qh[f][kc], kl_[2], kl_[3]);
                    mma16816(sD[f][2*np],   Ql[f][kc], kh[0],  kh[1]);
                    mma16816(sD[f][2*np+1], Ql[f][kc], kh[2],  kh[3]);
                }
            }
        }

        // ---- softmax: P = exp(S/8), pack hi/lo in registers ----
        uint32_t Ph[2][8][2], Pl[2][8][2];
#pragma unroll
        for (int f = 0; f < 2; ++f)
#pragma unroll
            for (int n = 0; n < 8; ++n) {
                float e0 = ex2f(sD[f][n][0] * CEXP);
                float e1 = ex2f(sD[f][n][1] * CEXP);
                float e2 = ex2f(sD[f][n][2] * CEXP);
                float e3 = ex2f(sD[f][n][3] * CEXP);
                lacc[f][0] += e0 + e1;
                lacc[f][1] += e2 + e3;
                packpair(e0, e1, Ph[f][n][0], Pl[f][n][0]);
                packpair(e2, e3, Ph[f][n][1], Pl[f][n][1]);
            }

        // ---- O += P V (3-pass) ----
        const int rV = ((l >> 3) & 1) * 8 + (l & 7);
        const int cVo = l >> 4;
#pragma unroll
        for (int np = 0; np < 4; ++np) {
#pragma unroll
            for (int kcv = 0; kcv < 4; ++kcv) {
                const int kk = 16 * kcv + rV;
                const int c  = 2 * np + cVo;
                const uint32_t a = uVH + kk * 128 + ((c ^ (kk & 7)) << 4);
                uint32_t vh[4], vl_[4];
                ldsm4t(vh, a);
                ldsm4t(vl_, a + 8192);
#pragma unroll
                for (int f = 0; f < 2; ++f) {
                    uint32_t Ah[4] = {Ph[f][2*kcv][0], Ph[f][2*kcv][1],
                                      Ph[f][2*kcv+1][0], Ph[f][2*kcv+1][1]};
                    uint32_t Al[4] = {Pl[f][2*kcv][0], Pl[f][2*kcv][1],
                                      Pl[f][2*kcv+1][0], Pl[f][2*kcv+1][1]};
                    mma16816(O[f][2*np],   Ah, vh[0],  vh[1]);
                    mma16816(O[f][2*np+1], Ah, vh[2],  vh[3]);
                    mma16816(O[f][2*np],   Ah, vl_[0], vl_[1]);
                    mma16816(O[f][2*np+1], Ah, vl_[2], vl_[3]);
                    mma16816(O[f][2*np],   Al, vh[0],  vh[1]);
                    mma16816(O[f][2*np+1], Al, vh[2],  vh[3]);
                }
            }
        }
    }

    // ---- write partial O and l ----
    lacc[0][0] += __shfl_xor_sync(0xffffffffu, lacc[0][0], 1);
    lacc[0][0] += __shfl_xor_sync(0xffffffffu, lacc[0][0], 2);
    lacc[0][1] += __shfl_xor_sync(0xffffffffu, lacc[0][1], 1);
    lacc[0][1] += __shfl_xor_sync(0xffffffffu, lacc[0][1], 2);
    lacc[1][0] += __shfl_xor_sync(0xffffffffu, lacc[1][0], 1);
    lacc[1][0] += __shfl_xor_sync(0xffffffffu, lacc[1][0], 2);
    lacc[1][1] += __shfl_xor_sync(0xffffffffu, lacc[1][1], 1);
    lacc[1][1] += __shfl_xor_sync(0xffffffffu, lacc[1][1], 2);

    float* op = g_Opart[split];
#pragma unroll
    for (int f = 0; f < 2; ++f) {
        const int row0 = qb * QB + w * 32 + f * 16 + (l >> 2);
        const int t    = l & 3;
#pragma unroll
        for (int n = 0; n < 8; ++n) {
            *reinterpret_cast<float2*>(op + (size_t)row0 * HD + 8 * n + 2 * t) =
                make_float2(O[f][n][0], O[f][n][1]);
            *reinterpret_cast<float2*>(op + (size_t)(row0 + 8) * HD + 8 * n + 2 * t) =
                make_float2(O[f][n][2], O[f][n][3]);
        }
        if ((l & 3) == 0) {
            g_lpart[split][row0]     = lacc[f][0];
            g_lpart[split][row0 + 8] = lacc[f][1];
        }
    }
}

// ---------------------------------------------------------------------------
// Kernel 3: fused combine + output GEMM (64x64 tiles, 4x4/thread, occ 2)
// ---------------------------------------------------------------------------
__device__ __forceinline__ int swz_w(int kk, int j) {
    return kk * 64 + ((((j >> 2) ^ ((kk >> 2) & 15)) << 2) | (j & 3));
}

__global__ __launch_bounds__(256, 2) void out_gemm(float* __restrict__ out) {
    __shared__ float sHT[4096];
    __shared__ float sW[4096];
    __shared__ float sInv[64];

    const int tid = threadIdx.x;
    const int tx = tid & 15;
    const int ty = tid >> 4;
    const int i0 = ty * 4;
    const int mBase = blockIdx.x * 64;
    const int nBase = blockIdx.y * 64;

    if (tid < 64)
        sInv[tid] = 1.0f / (g_lpart[0][mBase + tid] + g_lpart[1][mBase + tid]);
    __syncthreads();

    const float4* o0 = reinterpret_cast<const float4*>(g_Opart[0] + (size_t)mBase * HD);
    const float4* o1 = reinterpret_cast<const float4*>(g_Opart[1] + (size_t)mBase * HD);
    const float4* w4 = reinterpret_cast<const float4*>(g_wsum);
#pragma unroll
    for (int it = 0; it < 4; ++it) {
        int idx = tid + it * 256;
        int c4  = idx & 15;
        int rowi = idx >> 4;
        float4 a = o0[rowi * 16 + c4];
        float4 b = o1[rowi * 16 + c4];
        float inv = sInv[rowi];
        float vv[4] = {(a.x + b.x) * inv, (a.y + b.y) * inv,
                       (a.z + b.z) * inv, (a.w + b.w) * inv};
#pragma unroll
        for (int e = 0; e < 4; ++e)
            sHT[swz_w(c4 * 4 + e, rowi)] = vv[e];
        float4 wv = w4[rowi * 128 + (nBase >> 2) + c4];
        *reinterpret_cast<float4*>(&sW[rowi * 64 + c4 * 4]) = wv;
    }
    __syncthreads();

    float o[4][4];
#pragma unroll
    for (int rr = 0; rr < 4; ++rr)
#pragma unroll
        for (int cc = 0; cc < 4; ++cc) o[rr][cc] = 0.f;

#pragma unroll 8
    for (int kk = 0; kk < 64; ++kk) {
        int sw = (kk >> 2) & 15;
        float4 a = *reinterpret_cast<const float4*>(&sHT[kk * 64 + ((ty ^ sw) << 2)]);
        float4 b = *reinterpret_cast<const float4*>(&sW[kk * 64 + tx * 4]);
        float av[4] = {a.x, a.y, a.z, a.w};
        float bv[4] = {b.x, b.y, b.z, b.w};
#pragma unroll
        for (int rr = 0; rr < 4; ++rr)
#pragma unroll
            for (int cc = 0; cc < 4; ++cc)
                o[rr][cc] = fmaf(av[rr], bv[cc], o[rr][cc]);
    }

#pragma unroll
    for (int rr = 0; rr < 4; ++rr)
        *reinterpret_cast<float4*>(&out[(size_t)(mBase + i0 + rr) * WW + nBase + tx * 4]) =
            make_float4(o[rr][0], o[rr][1], o[rr][2], o[rr][3]);
}

// ---------------------------------------------------------------------------
extern "C" void kernel_launch(void* const* d_in, const int* in_sizes, int n_in,
                              void* d_out, int out_size) {
    const float* q   = (const float*)d_in[0];
    const float* k   = (const float*)d_in[1];
    const float* v   = (const float*)d_in[2];
    const float* w_o = (const float*)d_in[3];
    float* out = (float*)d_out;

    cudaFuncSetAttribute(attn_mma, cudaFuncAttributeMaxDynamicSharedMemorySize, 131072);

    convert_kernel<<<128, 256>>>(q, k, v);
    wsum_kernel<<<128, 256>>>(w_o);
    attn_mma<<<NQB * KSPLIT, 128, 131072>>>(q, k, v);
    out_gemm<<<dim3(S_LEN / 64, WW / 64), 256>>>(out);
}

// round 6
// speedup vs baseline: 1.2268x; 1.1395x over previous
#include <cuda_runtime.h>
#include <cuda_bf16.h>
#include <cstdint>

#define S_LEN 8192
#define HD 64
#define NHEADS 8
#define WW 512
#define KSPLIT 2
#define QB 128
#define NQB (S_LEN/QB)            /* 64 */
#define NKT ((S_LEN/KSPLIT)/64)   /* 64 key tiles of 64 */
#define CEXP 0.1803368801111204f  /* 0.125 * log2(e) */

static __device__ float g_wsum[HD * WW];
static __device__ float g_Opart[KSPLIT][S_LEN * HD];
static __device__ float g_lpart[KSPLIT][S_LEN];
// pre-converted bf16 hi/lo operands, [row][dim] linear
static __device__ __align__(16) __nv_bfloat16 g_qh[S_LEN * HD], g_ql[S_LEN * HD];
static __device__ __align__(16) __nv_bfloat16 g_kh[S_LEN * HD], g_kl[S_LEN * HD];
static __device__ __align__(16) __nv_bfloat16 g_vh[S_LEN * HD], g_vl[S_LEN * HD];

// ---------------- helpers ----------------
__device__ __forceinline__ uint32_t smem_u32(const void* p) {
    uint32_t a;
    asm("{ .reg .u64 t; cvta.to.shared.u64 t, %1; cvt.u32.u64 %0, t; }" : "=r"(a) : "l"(p));
    return a;
}
__device__ __forceinline__ void ldsm4(uint32_t* r, uint32_t a) {
    asm volatile("ldmatrix.sync.aligned.m8n8.x4.shared.b16 {%0,%1,%2,%3}, [%4];"
                 : "=r"(r[0]), "=r"(r[1]), "=r"(r[2]), "=r"(r[3]) : "r"(a));
}
__device__ __forceinline__ void ldsm4t(uint32_t* r, uint32_t a) {
    asm volatile("ldmatrix.sync.aligned.m8n8.x4.trans.shared.b16 {%0,%1,%2,%3}, [%4];"
                 : "=r"(r[0]), "=r"(r[1]), "=r"(r[2]), "=r"(r[3]) : "r"(a));
}
__device__ __forceinline__ void mma16816(float* d, const uint32_t* a, uint32_t b0, uint32_t b1) {
    asm volatile(
        "mma.sync.aligned.m16n8k16.row.col.f32.bf16.bf16.f32 "
        "{%0,%1,%2,%3}, {%4,%5,%6,%7}, {%8,%9}, {%0,%1,%2,%3};"
        : "+f"(d[0]), "+f"(d[1]), "+f"(d[2]), "+f"(d[3])
        : "r"(a[0]), "r"(a[1]), "r"(a[2]), "r"(a[3]), "r"(b0), "r"(b1));
}
__device__ __forceinline__ uint32_t bpack(float a, float b) {
    uint32_t r;
    asm("cvt.rn.bf16x2.f32 %0, %1, %2;" : "=r"(r) : "f"(b), "f"(a));
    return r;
}
__device__ __forceinline__ void packpair(float a, float b, uint32_t& hi, uint32_t& lo) {
    hi = bpack(a, b);
    float fa = __uint_as_float(hi << 16);
    float fb = __uint_as_float(hi & 0xFFFF0000u);
    lo = bpack(a - fa, b - fb);
}
__device__ __forceinline__ float ex2f(float x) {
    float y; asm("ex2.approx.f32 %0, %1;" : "=f"(y) : "f"(x)); return y;
}
#define CP_ASYNC16(dst, src) \
    asm volatile("cp.async.cg.shared.global [%0], [%1], 16;" :: "r"(dst), "l"(src))
#define CP_COMMIT() asm volatile("cp.async.commit_group;" ::: "memory")
#define CP_WAIT(n)  asm volatile("cp.async.wait_group %0;" :: "n"(n) : "memory")

// ---------------------------------------------------------------------------
// Kernel 0: convert q/k/v fp32 -> bf16 hi/lo (linear layout)
// ---------------------------------------------------------------------------
__device__ __forceinline__ void cvt16(const float4* s, __nv_bfloat16* h, __nv_bfloat16* lo) {
    float fv[16];
#pragma unroll
    for (int i = 0; i < 4; ++i) {
        float4 t = s[i];
        fv[4*i] = t.x; fv[4*i+1] = t.y; fv[4*i+2] = t.z; fv[4*i+3] = t.w;
    }
    uint32_t hh[8], ll[8];
#pragma unroll
    for (int p = 0; p < 8; ++p) packpair(fv[2*p], fv[2*p+1], hh[p], ll[p]);
    reinterpret_cast<uint4*>(h)[0]  = make_uint4(hh[0], hh[1], hh[2], hh[3]);
    reinterpret_cast<uint4*>(h)[1]  = make_uint4(hh[4], hh[5], hh[6], hh[7]);
    reinterpret_cast<uint4*>(lo)[0] = make_uint4(ll[0], ll[1], ll[2], ll[3]);
    reinterpret_cast<uint4*>(lo)[1] = make_uint4(ll[4], ll[5], ll[6], ll[7]);
}

__global__ void convert_kernel(const float* __restrict__ q, const float* __restrict__ k,
                               const float* __restrict__ v) {
    int t = blockIdx.x * blockDim.x + threadIdx.x;   // 0..32767
    int off = t * 16;
    cvt16(reinterpret_cast<const float4*>(q + off), g_qh + off, g_ql + off);
    cvt16(reinterpret_cast<const float4*>(k + off), g_kh + off, g_kl + off);
    cvt16(reinterpret_cast<const float4*>(v + off), g_vh + off, g_vl + off);
}

// ---------------------------------------------------------------------------
// Kernel 1: W_sum reduce
// ---------------------------------------------------------------------------
__global__ void wsum_kernel(const float* __restrict__ w_o) {
    int idx = blockIdx.x * blockDim.x + threadIdx.x;
    int d = idx >> 9;
    int c = idx & 511;
    float s = 0.f;
#pragma unroll
    for (int h = 0; h < NHEADS; ++h)
        s += w_o[(h * HD + d) * WW + c];
    g_wsum[idx] = s;
}

// ---------------------------------------------------------------------------
// Kernel 2: flash attention. 256 threads (8 warps x 16 rows), cp.async staging
// from pre-converted bf16, triple-buffered K/V.
// Smem: Q hi@0 lo@16384 (32KB); bufs @32768 + b*32768; buf: KH@0 KL@8K VH@16K VL@24K.
// ---------------------------------------------------------------------------
__device__ __forceinline__ void issue_tile(uint32_t bufBase, int kvRow0, int tid) {
    const int key = tid >> 2, sub = tid & 3;       // 64 keys, 4 threads/key
    const size_t gOff = (size_t)(kvRow0 + key) * HD;
    const __nv_bfloat16* srcs[4] = {g_kh, g_kl, g_vh, g_vl};
#pragma unroll
    for (int a = 0; a < 4; ++a) {
        const __nv_bfloat16* src = srcs[a] + gOff;
        const uint32_t dstRow = bufBase + a * 8192 + key * 128;
#pragma unroll
        for (int i = 0; i < 2; ++i) {
            const int ch = sub * 2 + i;
            CP_ASYNC16(dstRow + ((ch ^ (key & 7)) << 4), src + ch * 8);
        }
    }
}

__global__ __launch_bounds__(256, 1)
void attn_mma(const float* __restrict__ q, const float* __restrict__ k,
              const float* __restrict__ v) {
    extern __shared__ __align__(1024) unsigned char sm[];
    const int tid = threadIdx.x;
    const int w   = tid >> 5;
    const int l   = tid & 31;
    const int qb    = blockIdx.x & (NQB - 1);
    const int split = blockIdx.x >> 6;
    const int kvBase = split * (S_LEN / KSPLIT);
    const uint32_t smBase = smem_u32(sm);

    // ---- prologue: Q hi/lo via cp.async (2 threads per row) ----
    {
        const int row = tid >> 1, sel = tid & 1;
        const uint32_t dstRow = smBase + row * 128;
        const size_t gOff = (size_t)(qb * QB + row) * HD;
#pragma unroll
        for (int i = 0; i < 4; ++i) {
            const int ch = sel * 4 + i;
            CP_ASYNC16(dstRow + ((ch ^ (row & 7)) << 4), g_qh + gOff + ch * 8);
            CP_ASYNC16(dstRow + 16384 + ((ch ^ (row & 7)) << 4), g_ql + gOff + ch * 8);
        }
        CP_COMMIT();
    }
    issue_tile(smBase + 32768, kvBase, tid);          CP_COMMIT();
    issue_tile(smBase + 65536, kvBase + 64, tid);     CP_COMMIT();
    CP_WAIT(2);          // Q resident
    __syncthreads();

    // ---- persistent Q fragments (16 rows per warp) ----
    uint32_t Qh[4][4], Ql[4][4];
    {
        const int qrow = w * 16 + (l & 7) + ((l >> 3) & 1) * 8;
        const int hi8 = l >> 4;
#pragma unroll
        for (int kc = 0; kc < 4; ++kc) {
            const int c = 2 * kc + hi8;
            const uint32_t a = smBase + qrow * 128 + ((c ^ (qrow & 7)) << 4);
            ldsm4(Qh[kc], a);
            ldsm4(Ql[kc], a + 16384);
        }
    }

    float O[8][4];
#pragma unroll
    for (int n = 0; n < 8; ++n)
#pragma unroll
        for (int j = 0; j < 4; ++j) O[n][j] = 0.f;
    float lacc0 = 0.f, lacc1 = 0.f;

    const int r = l & 7;

    for (int kb = 0; kb < NKT; ++kb) {
        CP_WAIT(1);          // tile kb resident; kb+1 may be in flight
        __syncthreads();     // all warps done reading buf (kb+2)%3 (= tile kb-1)
        if (kb + 2 < NKT)
            issue_tile(smBase + 32768 + ((kb + 2) % 3) * 32768,
                       kvBase + (kb + 2) * 64, tid);
        CP_COMMIT();

        const uint32_t uKH = smBase + 32768 + (kb % 3) * 32768;
        const uint32_t uVH = uKH + 16384;

        // ---- S = Q K^T (3-pass split bf16) ----
        float sD[8][4];
#pragma unroll
        for (int n = 0; n < 8; ++n)
#pragma unroll
            for (int j = 0; j < 4; ++j) sD[n][j] = 0.f;

#pragma unroll
        for (int np = 0; np < 4; ++np) {
#pragma unroll
            for (int kc = 0; kc < 4; ++kc) {
                const int kk = 16 * np + (l >> 4) * 8 + r;
                const int c  = 2 * kc + ((l >> 3) & 1);
                const uint32_t a = uKH + kk * 128 + ((c ^ (kk & 7)) << 4);
                uint32_t kh[4], kl_[4];
                ldsm4(kh, a);
                ldsm4(kl_, a + 8192);
                mma16816(sD[2*np],   Qh[kc], kh[0],  kh[1]);
                mma16816(sD[2*np+1], Qh[kc], kh[2],  kh[3]);
                mma16816(sD[2*np],   Qh[kc], kl_[0], kl_[1]);
                mma16816(sD[2*np+1], Qh[kc], kl_[2], kl_[3]);
                mma16816(sD[2*np],   Ql[kc], kh[0],  kh[1]);
                mma16816(sD[2*np+1], Ql[kc], kh[2],  kh[3]);
            }
        }

        // ---- softmax: P = exp(S/8) in registers ----
        uint32_t Ph[8][2], Pl[8][2];
#pragma unroll
        for (int n = 0; n < 8; ++n) {
            float e0 = ex2f(sD[n][0] * CEXP);
            float e1 = ex2f(sD[n][1] * CEXP);
            float e2 = ex2f(sD[n][2] * CEXP);
            float e3 = ex2f(sD[n][3] * CEXP);
            lacc0 += e0 + e1;
            lacc1 += e2 + e3;
            packpair(e0, e1, Ph[n][0], Pl[n][0]);
            packpair(e2, e3, Ph[n][1], Pl[n][1]);
        }

        // ---- O += P V (3-pass) ----
#pragma unroll
        for (int np = 0; np < 4; ++np) {
#pragma unroll
            for (int kcv = 0; kcv < 4; ++kcv) {
                const int kk = 16 * kcv + ((l >> 3) & 1) * 8 + r;
                const int c  = 2 * np + (l >> 4);
                const uint32_t a = uVH + kk * 128 + ((c ^ (kk & 7)) << 4);
                uint32_t vh[4], vl_[4];
                ldsm4t(vh, a);
                ldsm4t(vl_, a + 8192);
                uint32_t Ah[4] = {Ph[2*kcv][0], Ph[2*kcv][1], Ph[2*kcv+1][0], Ph[2*kcv+1][1]};
                uint32_t Al[4] = {Pl[2*kcv][0], Pl[2*kcv][1], Pl[2*kcv+1][0], Pl[2*kcv+1][1]};
                mma16816(O[2*np],   Ah, vh[0],  vh[1]);
                mma16816(O[2*np+1], Ah, vh[2],  vh[3]);
                mma16816(O[2*np],   Ah, vl_[0], vl_[1]);
                mma16816(O[2*np+1], Ah, vl_[2], vl_[3]);
                mma16816(O[2*np],   Al, vh[0],  vh[1]);
                mma16816(O[2*np+1], Al, vh[2],  vh[3]);
            }
        }
    }

    // ---- write partial O ----
    {
        const int row0 = qb * QB + w * 16 + (l >> 2);
        const int t    = l & 3;
        float* op = g_Opart[split];
#pragma unroll
        for (int n = 0; n < 8; ++n) {
            *reinterpret_cast<float2*>(op + (size_t)row0 * HD + 8 * n + 2 * t) =
                make_float2(O[n][0], O[n][1]);
            *reinterpret_cast<float2*>(op + (size_t)(row0 + 8) * HD + 8 * n + 2 * t) =
                make_float2(O[n][2], O[n][3]);
        }
    }
    lacc0 += __shfl_xor_sync(0xffffffffu, lacc0, 1);
    lacc0 += __shfl_xor_sync(0xffffffffu, lacc0, 2);
    lacc1 += __shfl_xor_sync(0xffffffffu, lacc1, 1);
    lacc1 += __shfl_xor_sync(0xffffffffu, lacc1, 2);
    if ((l & 3) == 0) {
        const int row0 = qb * QB + w * 16 + (l >> 2);
        g_lpart[split][row0]     = lacc0;
        g_lpart[split][row0 + 8] = lacc1;
    }
}

// ---------------------------------------------------------------------------
// Kernel 3: fused combine + output GEMM (64x64 tiles, 4x4/thread, occ 2)
// ---------------------------------------------------------------------------
__device__ __forceinline__ int swz_w(int kk, int j) {
    return kk * 64 + ((((j >> 2) ^ ((kk >> 2) & 15)) << 2) | (j & 3));
}

__global__ __launch_bounds__(256, 2) void out_gemm(float* __restrict__ out) {
    __shared__ float sHT[4096];
    __shared__ float sW[4096];
    __shared__ float sInv[64];

    const int tid = threadIdx.x;
    const int tx = tid & 15;
    const int ty = tid >> 4;
    const int i0 = ty * 4;
    const int mBase = blockIdx.x * 64;
    const int nBase = blockIdx.y * 64;

    if (tid < 64)
        sInv[tid] = 1.0f / (g_lpart[0][mBase + tid] + g_lpart[1][mBase + tid]);
    __syncthreads();

    const float4* o0 = reinterpret_cast<const float4*>(g_Opart[0] + (size_t)mBase * HD);
    const float4* o1 = reinterpret_cast<const float4*>(g_Opart[1] + (size_t)mBase * HD);
    const float4* w4 = reinterpret_cast<const float4*>(g_wsum);
#pragma unroll
    for (int it = 0; it < 4; ++it) {
        int idx = tid + it * 256;
        int c4  = idx & 15;
        int rowi = idx >> 4;
        float4 a = o0[rowi * 16 + c4];
        float4 b = o1[rowi * 16 + c4];
        float inv = sInv[rowi];
        float vv[4] = {(a.x + b.x) * inv, (a.y + b.y) * inv,
                       (a.z + b.z) * inv, (a.w + b.w) * inv};
#pragma unroll
        for (int e = 0; e < 4; ++e)
            sHT[swz_w(c4 * 4 + e, rowi)] = vv[e];
        float4 wv = w4[rowi * 128 + (nBase >> 2) + c4];
        *reinterpret_cast<float4*>(&sW[rowi * 64 + c4 * 4]) = wv;
    }
    __syncthreads();

    float o[4][4];
#pragma unroll
    for (int rr = 0; rr < 4; ++rr)
#pragma unroll
        for (int cc = 0; cc < 4; ++cc) o[rr][cc] = 0.f;

#pragma unroll 8
    for (int kk = 0; kk < 64; ++kk) {
        int sw = (kk >> 2) & 15;
        float4 a = *reinterpret_cast<const float4*>(&sHT[kk * 64 + ((ty ^ sw) << 2)]);
        float4 b = *reinterpret_cast<const float4*>(&sW[kk * 64 + tx * 4]);
        float av[4] = {a.x, a.y, a.z, a.w};
        float bv[4] = {b.x, b.y, b.z, b.w};
#pragma unroll
        for (int rr = 0; rr < 4; ++rr)
#pragma unroll
            for (int cc = 0; cc < 4; ++cc)
                o[rr][cc] = fmaf(av[rr], bv[cc], o[rr][cc]);
    }

#pragma unroll
    for (int rr = 0; rr < 4; ++rr)
        *reinterpret_cast<float4*>(&out[(size_t)(mBase + i0 + rr) * WW + nBase + tx * 4]) =
            make_float4(o[rr][0], o[rr][1], o[rr][2], o[rr][3]);
}

// ---------------------------------------------------------------------------
extern "C" void kernel_launch(void* const* d_in, const int* in_sizes, int n_in,
                              void* d_out, int out_size) {
    const float* q   = (const float*)d_in[0];
    const float* k   = (const float*)d_in[1];
    const float* v   = (const float*)d_in[2];
    const float* w_o = (const float*)d_in[3];
    float* out = (float*)d_out;

    cudaFuncSetAttribute(attn_mma, cudaFuncAttributeMaxDynamicSharedMemorySize, 131072);

    convert_kernel<<<128, 256>>>(q, k, v);
    wsum_kernel<<<64, 512>>>(w_o);
    attn_mma<<<NQB * KSPLIT, 256, 131072>>>(q, k, v);
    out_gemm<<<dim3(S_LEN / 64, WW / 64), 256>>>(out);
}

// round 8
// speedup vs baseline: 1.9718x; 1.6073x over previous
#include <cuda_runtime.h>
#include <cuda_fp16.h>
#include <cstdint>

#define S_LEN 8192
#define HD 64
#define NHEADS 8
#define WW 512
#define KSPLIT 2
#define QB 128
#define NQB (S_LEN/QB)            /* 64 */
#define NKT ((S_LEN/KSPLIT)/64)   /* 64 key tiles of 64 */
#define CEXP 0.1803368801111204f  /* 0.125 * log2(e) */
#define ONES16 0x3C003C00u        /* fp16x2 {1,1} */

static __device__ float g_wsum[HD * WW];
static __device__ float g_Opart[KSPLIT][S_LEN * HD];
static __device__ float g_lpart[KSPLIT][S_LEN];
// pre-converted fp16 operands (q: hi+lo; k,v: hi only)
static __device__ __align__(16) __half g_qh[S_LEN * HD], g_ql[S_LEN * HD];
static __device__ __align__(16) __half g_kh[S_LEN * HD];
static __device__ __align__(16) __half g_vh[S_LEN * HD];

// ---------------- helpers ----------------
__device__ __forceinline__ uint32_t smem_u32(const void* p) {
    uint32_t a;
    asm("{ .reg .u64 t; cvta.to.shared.u64 t, %1; cvt.u32.u64 %0, t; }" : "=r"(a) : "l"(p));
    return a;
}
__device__ __forceinline__ void ldsm4(uint32_t* r, uint32_t a) {
    asm volatile("ldmatrix.sync.aligned.m8n8.x4.shared.b16 {%0,%1,%2,%3}, [%4];"
                 : "=r"(r[0]), "=r"(r[1]), "=r"(r[2]), "=r"(r[3]) : "r"(a));
}
__device__ __forceinline__ void ldsm4t(uint32_t* r, uint32_t a) {
    asm volatile("ldmatrix.sync.aligned.m8n8.x4.trans.shared.b16 {%0,%1,%2,%3}, [%4];"
                 : "=r"(r[0]), "=r"(r[1]), "=r"(r[2]), "=r"(r[3]) : "r"(a));
}
__device__ __forceinline__ void mma16816(float* d, const uint32_t* a, uint32_t b0, uint32_t b1) {
    asm volatile(
        "mma.sync.aligned.m16n8k16.row.col.f32.f16.f16.f32 "
        "{%0,%1,%2,%3}, {%4,%5,%6,%7}, {%8,%9}, {%0,%1,%2,%3};"
        : "+f"(d[0]), "+f"(d[1]), "+f"(d[2]), "+f"(d[3])
        : "r"(a[0]), "r"(a[1]), "r"(a[2]), "r"(a[3]), "r"(b0), "r"(b1));
}
// pack (a,b) -> fp16x2, a in low half
__device__ __forceinline__ uint32_t hpack(float a, float b) {
    __half2 h = __floats2half2_rn(a, b);
    return *reinterpret_cast<uint32_t*>(&h);
}
__device__ __forceinline__ void packpair(float a, float b, uint32_t& hi, uint32_t& lo) {
    __half2 h = __floats2half2_rn(a, b);
    hi = *reinterpret_cast<uint32_t*>(&h);
    float fa = __half2float(h.x);
    float fb = __half2float(h.y);
    lo = hpack(a - fa, b - fb);
}
__device__ __forceinline__ float ex2f(float x) {
    float y; asm("ex2.approx.f32 %0, %1;" : "=f"(y) : "f"(x)); return y;
}
#define CP_ASYNC16(dst, src) \
    asm volatile("cp.async.cg.shared.global [%0], [%1], 16;" :: "r"(dst), "l"(src))
#define CP_COMMIT() asm volatile("cp.async.commit_group;" ::: "memory")
#define CP_WAIT(n)  asm volatile("cp.async.wait_group %0;" :: "n"(n) : "memory")

// ---------------------------------------------------------------------------
// Kernel 0: convert q -> fp16 hi/lo; k,v -> fp16
// ---------------------------------------------------------------------------
__global__ void convert_kernel(const float* __restrict__ q, const float* __restrict__ k,
                               const float* __restrict__ v) {
    int t = blockIdx.x * blockDim.x + threadIdx.x;   // 0..32767
    int off = t * 16;
    {
        const float4* s = reinterpret_cast<const float4*>(q + off);
        float fv[16];
#pragma unroll
        for (int i = 0; i < 4; ++i) {
            float4 x = s[i];
            fv[4*i] = x.x; fv[4*i+1] = x.y; fv[4*i+2] = x.z; fv[4*i+3] = x.w;
        }
        uint32_t hh[8], ll[8];
#pragma unroll
        for (int p = 0; p < 8; ++p) packpair(fv[2*p], fv[2*p+1], hh[p], ll[p]);
        reinterpret_cast<uint4*>(g_qh + off)[0] = make_uint4(hh[0], hh[1], hh[2], hh[3]);
        reinterpret_cast<uint4*>(g_qh + off)[1] = make_uint4(hh[4], hh[5], hh[6], hh[7]);
        reinterpret_cast<uint4*>(g_ql + off)[0] = make_uint4(ll[0], ll[1], ll[2], ll[3]);
        reinterpret_cast<uint4*>(g_ql + off)[1] = make_uint4(ll[4], ll[5], ll[6], ll[7]);
    }
    {
        const float4* s = reinterpret_cast<const float4*>(k + off);
        uint32_t hh[8];
#pragma unroll
        for (int i = 0; i < 4; ++i) {
            float4 x = s[i];
            hh[2*i]   = hpack(x.x, x.y);
            hh[2*i+1] = hpack(x.z, x.w);
        }
        reinterpret_cast<uint4*>(g_kh + off)[0] = make_uint4(hh[0], hh[1], hh[2], hh[3]);
        reinterpret_cast<uint4*>(g_kh + off)[1] = make_uint4(hh[4], hh[5], hh[6], hh[7]);
    }
    {
        const float4* s = reinterpret_cast<const float4*>(v + off);
        uint32_t hh[8];
#pragma unroll
        for (int i = 0; i < 4; ++i) {
            float4 x = s[i];
            hh[2*i]   = hpack(x.x, x.y);
            hh[2*i+1] = hpack(x.z, x.w);
        }
        reinterpret_cast<uint4*>(g_vh + off)[0] = make_uint4(hh[0], hh[1], hh[2], hh[3]);
        reinterpret_cast<uint4*>(g_vh + off)[1] = make_uint4(hh[4], hh[5], hh[6], hh[7]);
    }
}

// ---------------------------------------------------------------------------
// Kernel 1: W_sum reduce
// ---------------------------------------------------------------------------
__global__ void wsum_kernel(const float* __restrict__ w_o) {
    int idx = blockIdx.x * blockDim.x + threadIdx.x;
    int d = idx >> 9;
    int c = idx & 511;
    float s = 0.f;
#pragma unroll
    for (int h = 0; h < NHEADS; ++h)
        s += w_o[(h * HD + d) * WW + c];
    g_wsum[idx] = s;
}

// ---------------------------------------------------------------------------
// Kernel 2: flash attention, fp16 MMA. 256 threads (8 warps x 16 rows),
// cp.async staging, triple-buffered KH/VH (16KB per buffer).
// Smem: Q hi@0 lo@16384 (32KB); buf b @ 32768 + b*16384: KH@0 VH@8192.
// ---------------------------------------------------------------------------
__device__ __forceinline__ void issue_tile(uint32_t bufBase, int kvRow0, int tid) {
    const int key = tid >> 2, sub = tid & 3;       // 64 keys, 4 threads/key
    const size_t gOff = (size_t)(kvRow0 + key) * HD;
#pragma unroll
    for (int i = 0; i < 2; ++i) {
        const int ch = sub * 2 + i;
        const uint32_t swo = ((ch ^ (key & 7)) << 4);
        CP_ASYNC16(bufBase + key * 128 + swo, g_kh + gOff + ch * 8);
        CP_ASYNC16(bufBase + 8192 + key * 128 + swo, g_vh + gOff + ch * 8);
    }
}

__global__ __launch_bounds__(256, 1)
void attn_mma(const float* __restrict__ q, const float* __restrict__ k,
              const float* __restrict__ v) {
    extern __shared__ __align__(1024) unsigned char sm[];
    const int tid = threadIdx.x;
    const int w   = tid >> 5;
    const int l   = tid & 31;
    const int qb    = blockIdx.x & (NQB - 1);
    const int split = blockIdx.x >> 6;
    const int kvBase = split * (S_LEN / KSPLIT);
    const uint32_t smBase = smem_u32(sm);

    // ---- prologue: Q hi/lo via cp.async (2 threads per row) ----
    {
        const int row = tid >> 1, sel = tid & 1;
        const uint32_t dstRow = smBase + row * 128;
        const size_t gOff = (size_t)(qb * QB + row) * HD;
#pragma unroll
        for (int i = 0; i < 4; ++i) {
            const int ch = sel * 4 + i;
            CP_ASYNC16(dstRow + ((ch ^ (row & 7)) << 4), g_qh + gOff + ch * 8);
            CP_ASYNC16(dstRow + 16384 + ((ch ^ (row & 7)) << 4), g_ql + gOff + ch * 8);
        }
        CP_COMMIT();
    }
    issue_tile(smBase + 32768, kvBase, tid);          CP_COMMIT();
    issue_tile(smBase + 49152, kvBase + 64, tid);     CP_COMMIT();
    CP_WAIT(2);          // Q resident
    __syncthreads();

    // ---- persistent Q fragments (16 rows per warp) ----
    uint32_t Qh[4][4], Ql[4][4];
    {
        const int qrow = w * 16 + (l & 7) + ((l >> 3) & 1) * 8;
        const int hi8 = l >> 4;
#pragma unroll
        for (int kc = 0; kc < 4; ++kc) {
            const int c = 2 * kc + hi8;
            const uint32_t a = smBase + qrow * 128 + ((c ^ (qrow & 7)) << 4);
            ldsm4(Qh[kc], a);
            ldsm4(Ql[kc], a + 16384);
        }
    }

    float O[8][4];
#pragma unroll
    for (int n = 0; n < 8; ++n)
#pragma unroll
        for (int j = 0; j < 4; ++j) O[n][j] = 0.f;
    float Lacc[4] = {0.f, 0.f, 0.f, 0.f};   // row-sum accumulator via ones-MMA

    const int r = l & 7;

    for (int kb = 0; kb < NKT; ++kb) {
        CP_WAIT(1);          // tile kb resident; kb+1 may be in flight
        __syncthreads();     // all warps done with buf (kb+2)%3 (= tile kb-1)
        if (kb + 2 < NKT)
            issue_tile(smBase + 32768 + ((kb + 2) % 3) * 16384,
                       kvBase + (kb + 2) * 64, tid);
        CP_COMMIT();

        const uint32_t uKH = smBase + 32768 + (kb % 3) * 16384;
        const uint32_t uVH = uKH + 8192;

        // ---- S = Q K^T (2-pass: qh*kh + ql*kh) ----
        float sD[8][4];
#pragma unroll
        for (int n = 0; n < 8; ++n)
#pragma unroll
            for (int j = 0; j < 4; ++j) sD[n][j] = 0.f;

#pragma unroll
        for (int np = 0; np < 4; ++np) {
#pragma unroll
            for (int kc = 0; kc < 4; ++kc) {
                const int kk = 16 * np + (l >> 4) * 8 + r;
                const int c  = 2 * kc + ((l >> 3) & 1);
                const uint32_t a = uKH + kk * 128 + ((c ^ (kk & 7)) << 4);
                uint32_t kh[4];
                ldsm4(kh, a);
                mma16816(sD[2*np],   Qh[kc], kh[0], kh[1]);
                mma16816(sD[2*np+1], Qh[kc], kh[2], kh[3]);
                mma16816(sD[2*np],   Ql[kc], kh[0], kh[1]);
                mma16816(sD[2*np+1], Ql[kc], kh[2], kh[3]);
            }
        }

        // ---- softmax: P = exp2(S * 0.125*log2e), fp32 ex2, pack fp16 ----
        uint32_t Ph[8][2];
#pragma unroll
        for (int n = 0; n < 8; ++n) {
            float e0 = ex2f(sD[n][0] * CEXP);
            float e1 = ex2f(sD[n][1] * CEXP);
            float e2 = ex2f(sD[n][2] * CEXP);
            float e3 = ex2f(sD[n][3] * CEXP);
            Ph[n][0] = hpack(e0, e1);
            Ph[n][1] = hpack(e2, e3);
        }

        // ---- O += P V (1-pass) and l += P @ ones (consistent with numerator) ----
#pragma unroll
        for (int kcv = 0; kcv < 4; ++kcv) {
            uint32_t Ah[4] = {Ph[2*kcv][0], Ph[2*kcv][1], Ph[2*kcv+1][0], Ph[2*kcv+1][1]};
            mma16816(Lacc, Ah, ONES16, ONES16);
            const int kk = 16 * kcv + ((l >> 3) & 1) * 8 + r;
#pragma unroll
            for (int np = 0; np < 4; ++np) {
                const int c = 2 * np + (l >> 4);
                const uint32_t a = uVH + kk * 128 + ((c ^ (kk & 7)) << 4);
                uint32_t vh[4];
                ldsm4t(vh, a);
                mma16816(O[2*np],   Ah, vh[0], vh[1]);
                mma16816(O[2*np+1], Ah, vh[2], vh[3]);
            }
        }
    }

    // ---- write partial O and l ----
    {
        const int row0 = qb * QB + w * 16 + (l >> 2);
        const int t    = l & 3;
        float* op = g_Opart[split];
#pragma unroll
        for (int n = 0; n < 8; ++n) {
            *reinterpret_cast<float2*>(op + (size_t)row0 * HD + 8 * n + 2 * t) =
                make_float2(O[n][0], O[n][1]);
            *reinterpret_cast<float2*>(op + (size_t)(row0 + 8) * HD + 8 * n + 2 * t) =
                make_float2(O[n][2], O[n][3]);
        }
        // ones-MMA: every column of Lacc equals the row sum; all 4 quad lanes agree
        if ((l & 3) == 0) {
            g_lpart[split][row0]     = Lacc[0];
            g_lpart[split][row0 + 8] = Lacc[2];
        }
    }
}

// ---------------------------------------------------------------------------
// Kernel 3: fused combine + output GEMM (64x64 tiles, 4x4/thread, occ 2)
// ---------------------------------------------------------------------------
__device__ __forceinline__ int swz_w(int kk, int j) {
    return kk * 64 + ((((j >> 2) ^ ((kk >> 2) & 15)) << 2) | (j & 3));
}

__global__ __launch_bounds__(256, 2) void out_gemm(float* __restrict__ out) {
    __shared__ float sHT[4096];
    __shared__ float sW[4096];
    __shared__ float sInv[64];

    const int tid = threadIdx.x;
    const int tx = tid & 15;
    const int ty = tid >> 4;
    const int i0 = ty * 4;
    const int mBase = blockIdx.x * 64;
    const int nBase = blockIdx.y * 64;

    if (tid < 64)
        sInv[tid] = 1.0f / (g_lpart[0][mBase + tid] + g_lpart[1][mBase + tid]);
    __syncthreads();

    const float4* o0 = reinterpret_cast<const float4*>(g_Opart[0] + (size_t)mBase * HD);
    const float4* o1 = reinterpret_cast<const float4*>(g_Opart[1] + (size_t)mBase * HD);
    const float4* w4 = reinterpret_cast<const float4*>(g_wsum);
#pragma unroll
    for (int it = 0; it < 4; ++it) {
        int idx = tid + it * 256;
        int c4  = idx & 15;
        int rowi = idx >> 4;
        float4 a = o0[rowi * 16 + c4];
        float4 b = o1[rowi * 16 + c4];
        float inv = sInv[rowi];
        float vv[4] = {(a.x + b.x) * inv, (a.y + b.y) * inv,
                       (a.z + b.z) * inv, (a.w + b.w) * inv};
#pragma unroll
        for (int e = 0; e < 4; ++e)
            sHT[swz_w(c4 * 4 + e, rowi)] = vv[e];
        float4 wv = w4[rowi * 128 + (nBase >> 2) + c4];
        *reinterpret_cast<float4*>(&sW[rowi * 64 + c4 * 4]) = wv;
    }
    __syncthreads();

    float o[4][4];
#pragma unroll
    for (int rr = 0; rr < 4; ++rr)
#pragma unroll
        for (int cc = 0; cc < 4; ++cc) o[rr][cc] = 0.f;

#pragma unroll 8
    for (int kk = 0; kk < 64; ++kk) {
        int sw = (kk >> 2) & 15;
        float4 a = *reinterpret_cast<const float4*>(&sHT[kk * 64 + ((ty ^ sw) << 2)]);
        float4 b = *reinterpret_cast<const float4*>(&sW[kk * 64 + tx * 4]);
        float av[4] = {a.x, a.y, a.z, a.w};
        float bv[4] = {b.x, b.y, b.z, b.w};
#pragma unroll
        for (int rr = 0; rr < 4; ++rr)
#pragma unroll
            for (int cc = 0; cc < 4; ++cc)
                o[rr][cc] = fmaf(av[rr], bv[cc], o[rr][cc]);
    }

#pragma unroll
    for (int rr = 0; rr < 4; ++rr)
        *reinterpret_cast<float4*>(&out[(size_t)(mBase + i0 + rr) * WW + nBase + tx * 4]) =
            make_float4(o[rr][0], o[rr][1], o[rr][2], o[rr][3]);
}

// ---------------------------------------------------------------------------
extern "C" void kernel_launch(void* const* d_in, const int* in_sizes, int n_in,
                              void* d_out, int out_size) {
    const float* q   = (const float*)d_in[0];
    const float* k   = (const float*)d_in[1];
    const float* v   = (const float*)d_in[2];
    const float* w_o = (const float*)d_in[3];
    float* out = (float*)d_out;

    cudaFuncSetAttribute(attn_mma, cudaFuncAttributeMaxDynamicSharedMemorySize, 81920);

    convert_kernel<<<128, 256>>>(q, k, v);
    wsum_kernel<<<64, 512>>>(w_o);
    attn_mma<<<NQB * KSPLIT, 256, 81920>>>(q, k, v);
    out_gemm<<<dim3(S_LEN / 64, WW / 64), 256>>>(out);
}

// round 9
// speedup vs baseline: 2.3187x; 1.1759x over previous
#include <cuda_runtime.h>
#include <cuda_fp16.h>
#include <cstdint>

#define S_LEN 8192
#define HD 64
#define NHEADS 8
#define WW 512
#define KSPLIT 2
#define QB 128
#define NQB (S_LEN/QB)            /* 64 */
#define NKT ((S_LEN/KSPLIT)/64)   /* 64 key tiles of 64 */
#define CEXP 0.1803368801111204f  /* 0.125 * log2(e) */
#define ONES16 0x3C003C00u        /* fp16x2 {1,1} */

static __device__ float g_Opart[KSPLIT][S_LEN * HD];
static __device__ float g_lpart[KSPLIT][S_LEN];
// pre-converted fp16 operands
static __device__ __align__(16) __half g_qh[S_LEN * HD];
static __device__ __align__(16) __half g_kh[S_LEN * HD];
static __device__ __align__(16) __half g_vh[S_LEN * HD];
// W_sum, fp16, transposed: [n=512][k=64] rows of 128B
static __device__ __align__(16) __half g_wht[WW * HD];

// ---------------- helpers ----------------
__device__ __forceinline__ uint32_t smem_u32(const void* p) {
    uint32_t a;
    asm("{ .reg .u64 t; cvta.to.shared.u64 t, %1; cvt.u32.u64 %0, t; }" : "=r"(a) : "l"(p));
    return a;
}
__device__ __forceinline__ void ldsm4(uint32_t* r, uint32_t a) {
    asm volatile("ldmatrix.sync.aligned.m8n8.x4.shared.b16 {%0,%1,%2,%3}, [%4];"
                 : "=r"(r[0]), "=r"(r[1]), "=r"(r[2]), "=r"(r[3]) : "r"(a));
}
__device__ __forceinline__ void ldsm4t(uint32_t* r, uint32_t a) {
    asm volatile("ldmatrix.sync.aligned.m8n8.x4.trans.shared.b16 {%0,%1,%2,%3}, [%4];"
                 : "=r"(r[0]), "=r"(r[1]), "=r"(r[2]), "=r"(r[3]) : "r"(a));
}
__device__ __forceinline__ void mma16816(float* d, const uint32_t* a, uint32_t b0, uint32_t b1) {
    asm volatile(
        "mma.sync.aligned.m16n8k16.row.col.f32.f16.f16.f32 "
        "{%0,%1,%2,%3}, {%4,%5,%6,%7}, {%8,%9}, {%0,%1,%2,%3};"
        : "+f"(d[0]), "+f"(d[1]), "+f"(d[2]), "+f"(d[3])
        : "r"(a[0]), "r"(a[1]), "r"(a[2]), "r"(a[3]), "r"(b0), "r"(b1));
}
__device__ __forceinline__ uint32_t hpack(float a, float b) {
    __half2 h = __floats2half2_rn(a, b);
    return *reinterpret_cast<uint32_t*>(&h);
}
__device__ __forceinline__ void packpair(float a, float b, uint32_t& hi, uint32_t& lo) {
    __half2 h = __floats2half2_rn(a, b);
    hi = *reinterpret_cast<uint32_t*>(&h);
    float fa = __half2float(h.x);
    float fb = __half2float(h.y);
    lo = hpack(a - fa, b - fb);
}
__device__ __forceinline__ float ex2f(float x) {
    float y; asm("ex2.approx.f32 %0, %1;" : "=f"(y) : "f"(x)); return y;
}
#define CP_ASYNC16(dst, src) \
    asm volatile("cp.async.cg.shared.global [%0], [%1], 16;" :: "r"(dst), "l"(src))
#define CP_COMMIT() asm volatile("cp.async.commit_group;" ::: "memory")
#define CP_WAIT(n)  asm volatile("cp.async.wait_group %0;" :: "n"(n) : "memory")

// ---------------------------------------------------------------------------
// Kernel 0: convert q,k,v -> fp16
// ---------------------------------------------------------------------------
__global__ void convert_kernel(const float* __restrict__ q, const float* __restrict__ k,
                               const float* __restrict__ v) {
    int t = blockIdx.x * blockDim.x + threadIdx.x;   // 0..32767
    int off = t * 16;
    const float* srcs[3] = {q, k, v};
    __half* dsts[3] = {g_qh, g_kh, g_vh};
#pragma unroll
    for (int a = 0; a < 3; ++a) {
        const float4* s = reinterpret_cast<const float4*>(srcs[a] + off);
        uint32_t hh[8];
#pragma unroll
        for (int i = 0; i < 4; ++i) {
            float4 x = s[i];
            hh[2*i]   = hpack(x.x, x.y);
            hh[2*i+1] = hpack(x.z, x.w);
        }
        reinterpret_cast<uint4*>(dsts[a] + off)[0] = make_uint4(hh[0], hh[1], hh[2], hh[3]);
        reinterpret_cast<uint4*>(dsts[a] + off)[1] = make_uint4(hh[4], hh[5], hh[6], hh[7]);
    }
}

// ---------------------------------------------------------------------------
// Kernel 1: W_sum reduce -> fp16, transposed [n][k]
// ---------------------------------------------------------------------------
__global__ void wsum_kernel(const float* __restrict__ w_o) {
    int idx = blockIdx.x * blockDim.x + threadIdx.x;   // 0..32767
    int d = idx >> 9;          // k in [0,64)
    int c = idx & 511;         // n in [0,512)
    float s = 0.f;
#pragma unroll
    for (int h = 0; h < NHEADS; ++h)
        s += w_o[(h * HD + d) * WW + c];
    g_wht[c * HD + d] = __float2half(s);
}

// ---------------------------------------------------------------------------
// Kernel 2: flash attention, fp16 MMA (1-pass S, 1-pass PV, ones-MMA l).
// 256 threads (8 warps x 16 rows), cp.async, triple-buffered KH/VH.
// Smem: Q@0 (16KB); buf b @ 16384 + b*16384: KH@0 VH@8192. Total 64KB.
// ---------------------------------------------------------------------------
__device__ __forceinline__ void issue_tile(uint32_t bufBase, int kvRow0, int tid) {
    const int key = tid >> 2, sub = tid & 3;       // 64 keys, 4 threads/key
    const size_t gOff = (size_t)(kvRow0 + key) * HD;
#pragma unroll
    for (int i = 0; i < 2; ++i) {
        const int ch = sub * 2 + i;
        const uint32_t swo = ((ch ^ (key & 7)) << 4);
        CP_ASYNC16(bufBase + key * 128 + swo, g_kh + gOff + ch * 8);
        CP_ASYNC16(bufBase + 8192 + key * 128 + swo, g_vh + gOff + ch * 8);
    }
}

__global__ __launch_bounds__(256, 1)
void attn_mma(const float* __restrict__ q, const float* __restrict__ k,
              const float* __restrict__ v) {
    extern __shared__ __align__(1024) unsigned char sm[];
    const int tid = threadIdx.x;
    const int w   = tid >> 5;
    const int l   = tid & 31;
    const int qb    = blockIdx.x & (NQB - 1);
    const int split = blockIdx.x >> 6;
    const int kvBase = split * (S_LEN / KSPLIT);
    const uint32_t smBase = smem_u32(sm);

    // ---- prologue: Q via cp.async (2 threads per row) ----
    {
        const int row = tid >> 1, sel = tid & 1;
        const uint32_t dstRow = smBase + row * 128;
        const size_t gOff = (size_t)(qb * QB + row) * HD;
#pragma unroll
        for (int i = 0; i < 4; ++i) {
            const int ch = sel * 4 + i;
            CP_ASYNC16(dstRow + ((ch ^ (row & 7)) << 4), g_qh + gOff + ch * 8);
        }
        CP_COMMIT();
    }
    issue_tile(smBase + 16384, kvBase, tid);          CP_COMMIT();
    issue_tile(smBase + 32768, kvBase + 64, tid);     CP_COMMIT();
    CP_WAIT(2);          // Q resident
    __syncthreads();

    // ---- persistent Q fragments (16 rows per warp) ----
    uint32_t Qh[4][4];
    {
        const int qrow = w * 16 + (l & 7) + ((l >> 3) & 1) * 8;
        const int hi8 = l >> 4;
#pragma unroll
        for (int kc = 0; kc < 4; ++kc) {
            const int c = 2 * kc + hi8;
            ldsm4(Qh[kc], smBase + qrow * 128 + ((c ^ (qrow & 7)) << 4));
        }
    }

    float O[8][4];
#pragma unroll
    for (int n = 0; n < 8; ++n)
#pragma unroll
        for (int j = 0; j < 4; ++j) O[n][j] = 0.f;
    float Lacc[4] = {0.f, 0.f, 0.f, 0.f};

    const int r = l & 7;

    for (int kb = 0; kb < NKT; ++kb) {
        CP_WAIT(1);
        __syncthreads();
        if (kb + 2 < NKT)
            issue_tile(smBase + 16384 + ((kb + 2) % 3) * 16384,
                       kvBase + (kb + 2) * 64, tid);
        CP_COMMIT();

        const uint32_t uKH = smBase + 16384 + (kb % 3) * 16384;
        const uint32_t uVH = uKH + 8192;

        // ---- S = Q K^T (1-pass) ----
        float sD[8][4];
#pragma unroll
        for (int n = 0; n < 8; ++n)
#pragma unroll
            for (int j = 0; j < 4; ++j) sD[n][j] = 0.f;

#pragma unroll
        for (int np = 0; np < 4; ++np) {
#pragma unroll
            for (int kc = 0; kc < 4; ++kc) {
                const int kk = 16 * np + (l >> 4) * 8 + r;
                const int c  = 2 * kc + ((l >> 3) & 1);
                uint32_t kh[4];
                ldsm4(kh, uKH + kk * 128 + ((c ^ (kk & 7)) << 4));
                mma16816(sD[2*np],   Qh[kc], kh[0], kh[1]);
                mma16816(sD[2*np+1], Qh[kc], kh[2], kh[3]);
            }
        }

        // ---- softmax: P = exp2(S * 0.125*log2e) ----
        uint32_t Ph[8][2];
#pragma unroll
        for (int n = 0; n < 8; ++n) {
            float e0 = ex2f(sD[n][0] * CEXP);
            float e1 = ex2f(sD[n][1] * CEXP);
            float e2 = ex2f(sD[n][2] * CEXP);
            float e3 = ex2f(sD[n][3] * CEXP);
            Ph[n][0] = hpack(e0, e1);
            Ph[n][1] = hpack(e2, e3);
        }

        // ---- O += P V; l += P @ ones ----
#pragma unroll
        for (int kcv = 0; kcv < 4; ++kcv) {
            uint32_t Ah[4] = {Ph[2*kcv][0], Ph[2*kcv][1], Ph[2*kcv+1][0], Ph[2*kcv+1][1]};
            mma16816(Lacc, Ah, ONES16, ONES16);
            const int kk = 16 * kcv + ((l >> 3) & 1) * 8 + r;
#pragma unroll
            for (int np = 0; np < 4; ++np) {
                const int c = 2 * np + (l >> 4);
                uint32_t vh[4];
                ldsm4t(vh, uVH + kk * 128 + ((c ^ (kk & 7)) << 4));
                mma16816(O[2*np],   Ah, vh[0], vh[1]);
                mma16816(O[2*np+1], Ah, vh[2], vh[3]);
            }
        }
    }

    // ---- write partial O and l ----
    {
        const int row0 = qb * QB + w * 16 + (l >> 2);
        const int t    = l & 3;
        float* op = g_Opart[split];
#pragma unroll
        for (int n = 0; n < 8; ++n) {
            *reinterpret_cast<float2*>(op + (size_t)row0 * HD + 8 * n + 2 * t) =
                make_float2(O[n][0], O[n][1]);
            *reinterpret_cast<float2*>(op + (size_t)(row0 + 8) * HD + 8 * n + 2 * t) =
                make_float2(O[n][2], O[n][3]);
        }
        if ((l & 3) == 0) {
            g_lpart[split][row0]     = Lacc[0];
            g_lpart[split][row0 + 8] = Lacc[2];
        }
    }
}

// ---------------------------------------------------------------------------
// Kernel 3: fused combine + output GEMM, fp16 MMA (head hi/lo 2-pass x Wh).
// Grid (128, 4): 64 rows x 128 cols per CTA, 128 threads (4 warps x 16 rows).
// Smem: Hhi@0 (8KB), Hlo@8192, W@16384 (16KB) = 32KB static.
// ---------------------------------------------------------------------------
__global__ __launch_bounds__(128, 2) void out_gemm(float* __restrict__ out) {
    __shared__ __align__(1024) unsigned char sg[32768];
    __shared__ float sInv[64];

    const int tid = threadIdx.x;
    const int w   = tid >> 5;
    const int l   = tid & 31;
    const int mBase = blockIdx.x * 64;
    const int nBase = blockIdx.y * 128;
    const uint32_t sb = smem_u32(sg);

    // ---- stage W tile via cp.async: 128 n-rows of 64 fp16 (128B), swizzled ----
    {
        const int nrow = tid;
        const __half* src = g_wht + (size_t)(nBase + nrow) * HD;
        const uint32_t dstRow = sb + 16384 + nrow * 128;
#pragma unroll
        for (int ch = 0; ch < 8; ++ch)
            CP_ASYNC16(dstRow + ((ch ^ (nrow & 7)) << 4), src + ch * 8);
        CP_COMMIT();
    }

    // ---- load O partials, compute inv-l ----
    const int row = tid >> 1, sel = tid & 1;     // 2 threads per row, 32 dims each
    float4 a4[8];
    {
        const float4* o0 = reinterpret_cast<const float4*>(
            g_Opart[0] + (size_t)(mBase + row) * HD + sel * 32);
        const float4* o1 = reinterpret_cast<const float4*>(
            g_Opart[1] + (size_t)(mBase + row) * HD + sel * 32);
#pragma unroll
        for (int i = 0; i < 8; ++i) a4[i] = o0[i];
#pragma unroll
        for (int i = 0; i < 8; ++i) {
            float4 b = o1[i];
            a4[i].x += b.x; a4[i].y += b.y; a4[i].z += b.z; a4[i].w += b.w;
        }
    }
    if (tid < 64)
        sInv[tid] = 1.0f / (g_lpart[0][mBase + tid] + g_lpart[1][mBase + tid]);
    __syncthreads();

    // ---- combine, pack hi/lo fp16, store swizzled ----
    {
        const float inv = sInv[row];
        float fv[32];
#pragma unroll
        for (int i = 0; i < 8; ++i) {
            fv[4*i]   = a4[i].x * inv; fv[4*i+1] = a4[i].y * inv;
            fv[4*i+2] = a4[i].z * inv; fv[4*i+3] = a4[i].w * inv;
        }
        const uint32_t dstRow = sb + row * 128;
#pragma unroll
        for (int g = 0; g < 4; ++g) {          // 4 chunks of 8 dims
            const int ch = sel * 4 + g;
            uint32_t hh[4], ll[4];
#pragma unroll
            for (int p = 0; p < 4; ++p)
                packpair(fv[8*g + 2*p], fv[8*g + 2*p + 1], hh[p], ll[p]);
            const uint32_t swo = ((ch ^ (row & 7)) << 4);
            *reinterpret_cast<uint4*>(sg + (row * 128 + swo)) =
                make_uint4(hh[0], hh[1], hh[2], hh[3]);
            *reinterpret_cast<uint4*>(sg + (8192 + row * 128 + swo)) =
                make_uint4(ll[0], ll[1], ll[2], ll[3]);
        }
    }
    CP_WAIT(0);
    __syncthreads();

    // ---- fragments & MMA ----
    uint32_t Hh[4][4], Hl[4][4];
    {
        const int hrow = w * 16 + (l & 7) + ((l >> 3) & 1) * 8;
        const int hi8 = l >> 4;
#pragma unroll
        for (int kc = 0; kc < 4; ++kc) {
            const int c = 2 * kc + hi8;
            const uint32_t addr = sb + hrow * 128 + ((c ^ (hrow & 7)) << 4);
            ldsm4(Hh[kc], addr);
            ldsm4(Hl[kc], addr + 8192);
        }
    }

    float oD[16][4];
#pragma unroll
    for (int n = 0; n < 16; ++n)
#pragma unroll
        for (int j = 0; j < 4; ++j) oD[n][j] = 0.f;

    const int r = l & 7;
#pragma unroll
    for (int np = 0; np < 8; ++np) {
#pragma unroll
        for (int kc = 0; kc < 4; ++kc) {
            const int kk = 16 * np + (l >> 4) * 8 + r;
            const int c  = 2 * kc + ((l >> 3) & 1);
            uint32_t b[4];
            ldsm4(b, sb + 16384 + kk * 128 + ((c ^ (kk & 7)) << 4));
            mma16816(oD[2*np],   Hh[kc], b[0], b[1]);
            mma16816(oD[2*np+1], Hh[kc], b[2], b[3]);
            mma16816(oD[2*np],   Hl[kc], b[0], b[1]);
            mma16816(oD[2*np+1], Hl[kc], b[2], b[3]);
        }
    }

    // ---- store ----
    {
        const int row0 = mBase + w * 16 + (l >> 2);
        const int t    = l & 3;
#pragma unroll
        for (int n = 0; n < 16; ++n) {
            const int col = nBase + 8 * n + 2 * t;
            *reinterpret_cast<float2*>(out + (size_t)row0 * WW + col) =
                make_float2(oD[n][0], oD[n][1]);
            *reinterpret_cast<float2*>(out + (size_t)(row0 + 8) * WW + col) =
                make_float2(oD[n][2], oD[n][3]);
        }
    }
}

// ---------------------------------------------------------------------------
extern "C" void kernel_launch(void* const* d_in, const int* in_sizes, int n_in,
                              void* d_out, int out_size) {
    const float* q   = (const float*)d_in[0];
    const float* k   = (const float*)d_in[1];
    const float* v   = (const float*)d_in[2];
    const float* w_o = (const float*)d_in[3];
    float* out = (float*)d_out;

    cudaFuncSetAttribute(attn_mma, cudaFuncAttributeMaxDynamicSharedMemorySize, 65536);

    convert_kernel<<<128, 256>>>(q, k, v);
    wsum_kernel<<<128, 256>>>(w_o);
    attn_mma<<<NQB * KSPLIT, 256, 65536>>>(q, k, v);
    out_gemm<<<dim3(S_LEN / 64, WW / 128), 128>>>(out);
}

// round 10
// speedup vs baseline: 2.4121x; 1.0403x over previous
#include <cuda_runtime.h>
#include <cuda_fp16.h>
#include <cstdint>

#define S_LEN 8192
#define HD 64
#define NHEADS 8
#define WW 512
#define KSPLIT 2
#define QB 128
#define NQB (S_LEN/QB)            /* 64 */
#define NKT ((S_LEN/KSPLIT)/64)   /* 64 key tiles of 64 */
#define CEXP 0.1803368801111204f  /* 0.125 * log2(e) */
#define ONES16 0x3C003C00u        /* fp16x2 {1,1} */

static __device__ float g_Opart[KSPLIT][S_LEN * HD];
static __device__ float g_lpart[KSPLIT][S_LEN];
static __device__ __align__(16) __half g_qh[S_LEN * HD];
static __device__ __align__(16) __half g_kh[S_LEN * HD];
static __device__ __align__(16) __half g_vh[S_LEN * HD];
// W_sum, fp16, transposed: [n=512][k=64] rows of 128B
static __device__ __align__(16) __half g_wht[WW * HD];

// ---------------- helpers ----------------
__device__ __forceinline__ uint32_t smem_u32(const void* p) {
    uint32_t a;
    asm("{ .reg .u64 t; cvta.to.shared.u64 t, %1; cvt.u32.u64 %0, t; }" : "=r"(a) : "l"(p));
    return a;
}
__device__ __forceinline__ void ldsm4(uint32_t* r, uint32_t a) {
    asm volatile("ldmatrix.sync.aligned.m8n8.x4.shared.b16 {%0,%1,%2,%3}, [%4];"
                 : "=r"(r[0]), "=r"(r[1]), "=r"(r[2]), "=r"(r[3]) : "r"(a));
}
__device__ __forceinline__ void ldsm4t(uint32_t* r, uint32_t a) {
    asm volatile("ldmatrix.sync.aligned.m8n8.x4.trans.shared.b16 {%0,%1,%2,%3}, [%4];"
                 : "=r"(r[0]), "=r"(r[1]), "=r"(r[2]), "=r"(r[3]) : "r"(a));
}
__device__ __forceinline__ void mma16816(float* d, const uint32_t* a, uint32_t b0, uint32_t b1) {
    asm volatile(
        "mma.sync.aligned.m16n8k16.row.col.f32.f16.f16.f32 "
        "{%0,%1,%2,%3}, {%4,%5,%6,%7}, {%8,%9}, {%0,%1,%2,%3};"
        : "+f"(d[0]), "+f"(d[1]), "+f"(d[2]), "+f"(d[3])
        : "r"(a[0]), "r"(a[1]), "r"(a[2]), "r"(a[3]), "r"(b0), "r"(b1));
}
__device__ __forceinline__ uint32_t hpack(float a, float b) {
    __half2 h = __floats2half2_rn(a, b);
    return *reinterpret_cast<uint32_t*>(&h);
}
__device__ __forceinline__ void packpair(float a, float b, uint32_t& hi, uint32_t& lo) {
    __half2 h = __floats2half2_rn(a, b);
    hi = *reinterpret_cast<uint32_t*>(&h);
    float fa = __half2float(h.x);
    float fb = __half2float(h.y);
    lo = hpack(a - fa, b - fb);
}
__device__ __forceinline__ float ex2f(float x) {
    float y; asm("ex2.approx.f32 %0, %1;" : "=f"(y) : "f"(x)); return y;
}
#define CP_ASYNC16(dst, src) \
    asm volatile("cp.async.cg.shared.global [%0], [%1], 16;" :: "r"(dst), "l"(src))
#define CP_COMMIT() asm volatile("cp.async.commit_group;" ::: "memory")
#define CP_WAIT(n)  asm volatile("cp.async.wait_group %0;" :: "n"(n) : "memory")

// ---------------------------------------------------------------------------
// Kernel 0 (merged prologue): blocks 0..127 convert q/k/v -> fp16;
// blocks 128..255 reduce w_o -> fp16 transposed W_sum.
// ---------------------------------------------------------------------------
__global__ void prologue_kernel(const float* __restrict__ q, const float* __restrict__ k,
                                const float* __restrict__ v, const float* __restrict__ w_o) {
    if (blockIdx.x < 128) {
        int t = blockIdx.x * blockDim.x + threadIdx.x;   // 0..32767
        int off = t * 16;
        const float* srcs[3] = {q, k, v};
        __half* dsts[3] = {g_qh, g_kh, g_vh};
#pragma unroll
        for (int a = 0; a < 3; ++a) {
            const float4* s = reinterpret_cast<const float4*>(srcs[a] + off);
            uint32_t hh[8];
#pragma unroll
            for (int i = 0; i < 4; ++i) {
                float4 x = s[i];
                hh[2*i]   = hpack(x.x, x.y);
                hh[2*i+1] = hpack(x.z, x.w);
            }
            reinterpret_cast<uint4*>(dsts[a] + off)[0] = make_uint4(hh[0], hh[1], hh[2], hh[3]);
            reinterpret_cast<uint4*>(dsts[a] + off)[1] = make_uint4(hh[4], hh[5], hh[6], hh[7]);
        }
    } else {
        int idx = (blockIdx.x - 128) * blockDim.x + threadIdx.x;   // 0..32767
        int d = idx >> 9;          // k in [0,64)
        int c = idx & 511;         // n in [0,512)
        float s = 0.f;
#pragma unroll
        for (int h = 0; h < NHEADS; ++h)
            s += w_o[(h * HD + d) * WW + c];
        g_wht[c * HD + d] = __float2half(s);
    }
}

// ---------------------------------------------------------------------------
// Kernel 1: flash attention, fp16 MMA (1-pass S, 1-pass PV, ones-MMA l).
// 256 threads (8 warps x 16 rows), cp.async, triple-buffered KH/VH.
// Smem: Q@0 (16KB); buf b @ 16384 + b*16384: KH@0 VH@8192. Total 64KB.
// ---------------------------------------------------------------------------
__device__ __forceinline__ void issue_tile(uint32_t bufBase, int kvRow0, int tid) {
    const int key = tid >> 2, sub = tid & 3;
    const size_t gOff = (size_t)(kvRow0 + key) * HD;
#pragma unroll
    for (int i = 0; i < 2; ++i) {
        const int ch = sub * 2 + i;
        const uint32_t swo = ((ch ^ (key & 7)) << 4);
        CP_ASYNC16(bufBase + key * 128 + swo, g_kh + gOff + ch * 8);
        CP_ASYNC16(bufBase + 8192 + key * 128 + swo, g_vh + gOff + ch * 8);
    }
}

__global__ __launch_bounds__(256, 1)
void attn_mma(const float* __restrict__ q, const float* __restrict__ k,
              const float* __restrict__ v) {
    extern __shared__ __align__(1024) unsigned char sm[];
    const int tid = threadIdx.x;
    const int w   = tid >> 5;
    const int l   = tid & 31;
    const int qb    = blockIdx.x & (NQB - 1);
    const int split = blockIdx.x >> 6;
    const int kvBase = split * (S_LEN / KSPLIT);
    const uint32_t smBase = smem_u32(sm);

    // ---- prologue: Q via cp.async ----
    {
        const int row = tid >> 1, sel = tid & 1;
        const uint32_t dstRow = smBase + row * 128;
        const size_t gOff = (size_t)(qb * QB + row) * HD;
#pragma unroll
        for (int i = 0; i < 4; ++i) {
            const int ch = sel * 4 + i;
            CP_ASYNC16(dstRow + ((ch ^ (row & 7)) << 4), g_qh + gOff + ch * 8);
        }
        CP_COMMIT();
    }
    issue_tile(smBase + 16384, kvBase, tid);          CP_COMMIT();
    issue_tile(smBase + 32768, kvBase + 64, tid);     CP_COMMIT();
    CP_WAIT(2);
    __syncthreads();

    uint32_t Qh[4][4];
    {
        const int qrow = w * 16 + (l & 7) + ((l >> 3) & 1) * 8;
        const int hi8 = l >> 4;
#pragma unroll
        for (int kc = 0; kc < 4; ++kc) {
            const int c = 2 * kc + hi8;
            ldsm4(Qh[kc], smBase + qrow * 128 + ((c ^ (qrow & 7)) << 4));
        }
    }

    float O[8][4];
#pragma unroll
    for (int n = 0; n < 8; ++n)
#pragma unroll
        for (int j = 0; j < 4; ++j) O[n][j] = 0.f;
    float Lacc[4] = {0.f, 0.f, 0.f, 0.f};

    const int r = l & 7;

    for (int kb = 0; kb < NKT; ++kb) {
        CP_WAIT(1);
        __syncthreads();
        if (kb + 2 < NKT)
            issue_tile(smBase + 16384 + ((kb + 2) % 3) * 16384,
                       kvBase + (kb + 2) * 64, tid);
        CP_COMMIT();

        const uint32_t uKH = smBase + 16384 + (kb % 3) * 16384;
        const uint32_t uVH = uKH + 8192;

        float sD[8][4];
#pragma unroll
        for (int n = 0; n < 8; ++n)
#pragma unroll
            for (int j = 0; j < 4; ++j) sD[n][j] = 0.f;

#pragma unroll
        for (int np = 0; np < 4; ++np) {
#pragma unroll
            for (int kc = 0; kc < 4; ++kc) {
                const int kk = 16 * np + (l >> 4) * 8 + r;
                const int c  = 2 * kc + ((l >> 3) & 1);
                uint32_t kh[4];
                ldsm4(kh, uKH + kk * 128 + ((c ^ (kk & 7)) << 4));
                mma16816(sD[2*np],   Qh[kc], kh[0], kh[1]);
                mma16816(sD[2*np+1], Qh[kc], kh[2], kh[3]);
            }
        }

        uint32_t Ph[8][2];
#pragma unroll
        for (int n = 0; n < 8; ++n) {
            float e0 = ex2f(sD[n][0] * CEXP);
            float e1 = ex2f(sD[n][1] * CEXP);
            float e2 = ex2f(sD[n][2] * CEXP);
            float e3 = ex2f(sD[n][3] * CEXP);
            Ph[n][0] = hpack(e0, e1);
            Ph[n][1] = hpack(e2, e3);
        }

#pragma unroll
        for (int kcv = 0; kcv < 4; ++kcv) {
            uint32_t Ah[4] = {Ph[2*kcv][0], Ph[2*kcv][1], Ph[2*kcv+1][0], Ph[2*kcv+1][1]};
            mma16816(Lacc, Ah, ONES16, ONES16);
            const int kk = 16 * kcv + ((l >> 3) & 1) * 8 + r;
#pragma unroll
            for (int np = 0; np < 4; ++np) {
                const int c = 2 * np + (l >> 4);
                uint32_t vh[4];
                ldsm4t(vh, uVH + kk * 128 + ((c ^ (kk & 7)) << 4));
                mma16816(O[2*np],   Ah, vh[0], vh[1]);
                mma16816(O[2*np+1], Ah, vh[2], vh[3]);
            }
        }
    }

    {
        const int row0 = qb * QB + w * 16 + (l >> 2);
        const int t    = l & 3;
        float* op = g_Opart[split];
#pragma unroll
        for (int n = 0; n < 8; ++n) {
            *reinterpret_cast<float2*>(op + (size_t)row0 * HD + 8 * n + 2 * t) =
                make_float2(O[n][0], O[n][1]);
            *reinterpret_cast<float2*>(op + (size_t)(row0 + 8) * HD + 8 * n + 2 * t) =
                make_float2(O[n][2], O[n][3]);
        }
        if ((l & 3) == 0) {
            g_lpart[split][row0]     = Lacc[0];
            g_lpart[split][row0 + 8] = Lacc[2];
        }
    }
}

// ---------------------------------------------------------------------------
// Kernel 2: fused combine + output GEMM, fp16 MMA (head hi/lo 2-pass x Wh).
// Grid (64, 4): 128 rows x 128 cols per CTA, 256 threads (8 warps x 16 rows).
// Smem: Hhi@0 (16KB), Hlo@16384 (16KB), W@32768 (16KB) = 48KB static.
// ---------------------------------------------------------------------------
__global__ __launch_bounds__(256) void out_gemm(float* __restrict__ out) {
    __shared__ __align__(1024) unsigned char sg[49152];
    __shared__ float sInv[128];

    const int tid = threadIdx.x;
    const int w   = tid >> 5;
    const int l   = tid & 31;
    const int mBase = blockIdx.x * 128;
    const int nBase = blockIdx.y * 128;
    const uint32_t sb = smem_u32(sg);

    // ---- stage W tile via cp.async: 128 n-rows x 64 fp16, swizzled ----
    {
        const int nrow = tid >> 1, sel = tid & 1;
        const __half* src = g_wht + (size_t)(nBase + nrow) * HD;
        const uint32_t dstRow = sb + 32768 + nrow * 128;
#pragma unroll
        for (int i = 0; i < 4; ++i) {
            const int ch = sel * 4 + i;
            CP_ASYNC16(dstRow + ((ch ^ (nrow & 7)) << 4), src + ch * 8);
        }
        CP_COMMIT();
    }

    // ---- load O partials (128 rows, 2 threads/row, 32 dims each) ----
    const int row = tid >> 1, sel = tid & 1;
    float4 a4[8];
    {
        const float4* o0 = reinterpret_cast<const float4*>(
            g_Opart[0] + (size_t)(mBase + row) * HD + sel * 32);
        const float4* o1 = reinterpret_cast<const float4*>(
            g_Opart[1] + (size_t)(mBase + row) * HD + sel * 32);
#pragma unroll
        for (int i = 0; i < 8; ++i) a4[i] = o0[i];
#pragma unroll
        for (int i = 0; i < 8; ++i) {
            float4 b = o1[i];
            a4[i].x += b.x; a4[i].y += b.y; a4[i].z += b.z; a4[i].w += b.w;
        }
    }
    if (tid < 128)
        sInv[tid] = 1.0f / (g_lpart[0][mBase + tid] + g_lpart[1][mBase + tid]);
    __syncthreads();

    // ---- combine, pack hi/lo fp16, store swizzled ----
    {
        const float inv = sInv[row];
        float fv[32];
#pragma unroll
        for (int i = 0; i < 8; ++i) {
            fv[4*i]   = a4[i].x * inv; fv[4*i+1] = a4[i].y * inv;
            fv[4*i+2] = a4[i].z * inv; fv[4*i+3] = a4[i].w * inv;
        }
        const uint32_t rowOff = row * 128;
#pragma unroll
        for (int g = 0; g < 4; ++g) {
            const int ch = sel * 4 + g;
            uint32_t hh[4], ll[4];
#pragma unroll
            for (int p = 0; p < 4; ++p)
                packpair(fv[8*g + 2*p], fv[8*g + 2*p + 1], hh[p], ll[p]);
            const uint32_t swo = ((ch ^ (row & 7)) << 4);
            *reinterpret_cast<uint4*>(sg + (rowOff + swo)) =
                make_uint4(hh[0], hh[1], hh[2], hh[3]);
            *reinterpret_cast<uint4*>(sg + (16384 + rowOff + swo)) =
                make_uint4(ll[0], ll[1], ll[2], ll[3]);
        }
    }
    CP_WAIT(0);
    __syncthreads();

    // ---- fragments & MMA ----
    uint32_t Hh[4][4], Hl[4][4];
    {
        const int hrow = w * 16 + (l & 7) + ((l >> 3) & 1) * 8;
        const int hi8 = l >> 4;
#pragma unroll
        for (int kc = 0; kc < 4; ++kc) {
            const int c = 2 * kc + hi8;
            const uint32_t addr = sb + hrow * 128 + ((c ^ (hrow & 7)) << 4);
            ldsm4(Hh[kc], addr);
            ldsm4(Hl[kc], addr + 16384);
        }
    }

    float oD[16][4];
#pragma unroll
    for (int n = 0; n < 16; ++n)
#pragma unroll
        for (int j = 0; j < 4; ++j) oD[n][j] = 0.f;

    const int r = l & 7;
#pragma unroll
    for (int np = 0; np < 8; ++np) {
#pragma unroll
        for (int kc = 0; kc < 4; ++kc) {
            const int kk = 16 * np + (l >> 4) * 8 + r;
            const int c  = 2 * kc + ((l >> 3) & 1);
            uint32_t b[4];
            ldsm4(b, sb + 32768 + kk * 128 + ((c ^ (kk & 7)) << 4));
            mma16816(oD[2*np],   Hh[kc], b[0], b[1]);
            mma16816(oD[2*np+1], Hh[kc], b[2], b[3]);
            mma16816(oD[2*np],   Hl[kc], b[0], b[1]);
            mma16816(oD[2*np+1], Hl[kc], b[2], b[3]);
        }
    }

    // ---- store ----
    {
        const int row0 = mBase + w * 16 + (l >> 2);
        const int t    = l & 3;
#pragma unroll
        for (int n = 0; n < 16; ++n) {
            const int col = nBase + 8 * n + 2 * t;
            *reinterpret_cast<float2*>(out + (size_t)row0 * WW + col) =
                make_float2(oD[n][0], oD[n][1]);
            *reinterpret_cast<float2*>(out + (size_t)(row0 + 8) * WW + col) =
                make_float2(oD[n][2], oD[n][3]);
        }
    }
}

// ---------------------------------------------------------------------------
extern "C" void kernel_launch(void* const* d_in, const int* in_sizes, int n_in,
                              void* d_out, int out_size) {
    const float* q   = (const float*)d_in[0];
    const float* k   = (const float*)d_in[1];
    const float* v   = (const float*)d_in[2];
    const float* w_o = (const float*)d_in[3];
    float* out = (float*)d_out;

    cudaFuncSetAttribute(attn_mma, cudaFuncAttributeMaxDynamicSharedMemorySize, 65536);

    prologue_kernel<<<256, 256>>>(q, k, v, w_o);
    attn_mma<<<NQB * KSPLIT, 256, 65536>>>(q, k, v);
    out_gemm<<<dim3(S_LEN / 128, WW / 128), 256>>>(out);
}

// round 11
// speedup vs baseline: 2.4536x; 1.0172x over previous
#include <cuda_runtime.h>
#include <cuda_fp16.h>
#include <cstdint>

#define S_LEN 8192
#define HD 64
#define NHEADS 8
#define WW 512
#define KSPLIT 2
#define QB 128
#define NQB (S_LEN/QB)            /* 64 */
#define NKT ((S_LEN/KSPLIT)/64)   /* 64 key tiles of 64 */
#define CEXP 0.1803368801111204f  /* 0.125 * log2(e) */
#define ONES16 0x3C003C00u        /* fp16x2 {1,1} */

static __device__ float g_Opart[KSPLIT][S_LEN * HD];
static __device__ float g_lpart[KSPLIT][S_LEN];
static __device__ __align__(16) __half g_qh[S_LEN * HD];
static __device__ __align__(16) __half g_kh[S_LEN * HD];
static __device__ __align__(16) __half g_vh[S_LEN * HD];
// W_sum, fp16, transposed: [n=512][k=64] rows of 128B
static __device__ __align__(16) __half g_wht[WW * HD];

// ---------------- helpers ----------------
__device__ __forceinline__ uint32_t smem_u32(const void* p) {
    uint32_t a;
    asm("{ .reg .u64 t; cvta.to.shared.u64 t, %1; cvt.u32.u64 %0, t; }" : "=r"(a) : "l"(p));
    return a;
}
__device__ __forceinline__ void ldsm4(uint32_t* r, uint32_t a) {
    asm volatile("ldmatrix.sync.aligned.m8n8.x4.shared.b16 {%0,%1,%2,%3}, [%4];"
                 : "=r"(r[0]), "=r"(r[1]), "=r"(r[2]), "=r"(r[3]) : "r"(a));
}
__device__ __forceinline__ void ldsm4t(uint32_t* r, uint32_t a) {
    asm volatile("ldmatrix.sync.aligned.m8n8.x4.trans.shared.b16 {%0,%1,%2,%3}, [%4];"
                 : "=r"(r[0]), "=r"(r[1]), "=r"(r[2]), "=r"(r[3]) : "r"(a));
}
__device__ __forceinline__ void mma16816(float* d, const uint32_t* a, uint32_t b0, uint32_t b1) {
    asm volatile(
        "mma.sync.aligned.m16n8k16.row.col.f32.f16.f16.f32 "
        "{%0,%1,%2,%3}, {%4,%5,%6,%7}, {%8,%9}, {%0,%1,%2,%3};"
        : "+f"(d[0]), "+f"(d[1]), "+f"(d[2]), "+f"(d[3])
        : "r"(a[0]), "r"(a[1]), "r"(a[2]), "r"(a[3]), "r"(b0), "r"(b1));
}
__device__ __forceinline__ uint32_t hpack(float a, float b) {
    __half2 h = __floats2half2_rn(a, b);
    return *reinterpret_cast<uint32_t*>(&h);
}
__device__ __forceinline__ void packpair(float a, float b, uint32_t& hi, uint32_t& lo) {
    __half2 h = __floats2half2_rn(a, b);
    hi = *reinterpret_cast<uint32_t*>(&h);
    float fa = __half2float(h.x);
    float fb = __half2float(h.y);
    lo = hpack(a - fa, b - fb);
}
__device__ __forceinline__ float ex2f(float x) {
    float y; asm("ex2.approx.f32 %0, %1;" : "=f"(y) : "f"(x)); return y;
}
#define CP_ASYNC16(dst, src) \
    asm volatile("cp.async.cg.shared.global [%0], [%1], 16;" :: "r"(dst), "l"(src))
#define CP_COMMIT() asm volatile("cp.async.commit_group;" ::: "memory")
#define CP_WAIT(n)  asm volatile("cp.async.wait_group %0;" :: "n"(n) : "memory")

// ---------------------------------------------------------------------------
// Kernel 0 (merged prologue): blocks 0..255 convert q/k/v (8 elems/thread);
// blocks 256..383 reduce w_o -> fp16 transposed W_sum.
// ---------------------------------------------------------------------------
__global__ void prologue_kernel(const float* __restrict__ q, const float* __restrict__ k,
                                const float* __restrict__ v, const float* __restrict__ w_o) {
    if (blockIdx.x < 256) {
        int t = blockIdx.x * blockDim.x + threadIdx.x;   // 0..65535
        int off = t * 8;
        const float* srcs[3] = {q, k, v};
        __half* dsts[3] = {g_qh, g_kh, g_vh};
#pragma unroll
        for (int a = 0; a < 3; ++a) {
            const float4* s = reinterpret_cast<const float4*>(srcs[a] + off);
            float4 x0 = s[0], x1 = s[1];
            reinterpret_cast<uint4*>(dsts[a] + off)[0] =
                make_uint4(hpack(x0.x, x0.y), hpack(x0.z, x0.w),
                           hpack(x1.x, x1.y), hpack(x1.z, x1.w));
        }
    } else {
        int idx = (blockIdx.x - 256) * blockDim.x + threadIdx.x;   // 0..32767
        int d = idx >> 9;          // k in [0,64)
        int c = idx & 511;         // n in [0,512)
        float s = 0.f;
#pragma unroll
        for (int h = 0; h < NHEADS; ++h)
            s += w_o[(h * HD + d) * WW + c];
        g_wht[c * HD + d] = __float2half(s);
    }
}

// ---------------------------------------------------------------------------
// Kernel 1: flash attention, fp16 MMA, np-chunked software pipeline so MUFU
// exp overlaps HMMA. 256 threads (8 warps x 16 rows), cp.async, triple-buffer.
// Smem: Q@0 (16KB); buf b @ 16384 + b*16384: KH@0 VH@8192. Total 64KB.
// ---------------------------------------------------------------------------
__device__ __forceinline__ void issue_tile(uint32_t bufBase, int kvRow0, int tid) {
    const int key = tid >> 2, sub = tid & 3;
    const size_t gOff = (size_t)(kvRow0 + key) * HD;
#pragma unroll
    for (int i = 0; i < 2; ++i) {
        const int ch = sub * 2 + i;
        const uint32_t swo = ((ch ^ (key & 7)) << 4);
        CP_ASYNC16(bufBase + key * 128 + swo, g_kh + gOff + ch * 8);
        CP_ASYNC16(bufBase + 8192 + key * 128 + swo, g_vh + gOff + ch * 8);
    }
}

__global__ __launch_bounds__(256, 1)
void attn_mma(const float* __restrict__ q, const float* __restrict__ k,
              const float* __restrict__ v) {
    extern __shared__ __align__(1024) unsigned char sm[];
    const int tid = threadIdx.x;
    const int w   = tid >> 5;
    const int l   = tid & 31;
    const int qb    = blockIdx.x & (NQB - 1);
    const int split = blockIdx.x >> 6;
    const int kvBase = split * (S_LEN / KSPLIT);
    const uint32_t smBase = smem_u32(sm);

    // ---- prologue: Q via cp.async ----
    {
        const int row = tid >> 1, sel = tid & 1;
        const uint32_t dstRow = smBase + row * 128;
        const size_t gOff = (size_t)(qb * QB + row) * HD;
#pragma unroll
        for (int i = 0; i < 4; ++i) {
            const int ch = sel * 4 + i;
            CP_ASYNC16(dstRow + ((ch ^ (row & 7)) << 4), g_qh + gOff + ch * 8);
        }
        CP_COMMIT();
    }
    issue_tile(smBase + 16384, kvBase, tid);          CP_COMMIT();
    issue_tile(smBase + 32768, kvBase + 64, tid);     CP_COMMIT();
    CP_WAIT(2);
    __syncthreads();

    uint32_t Qh[4][4];
    {
        const int qrow = w * 16 + (l & 7) + ((l >> 3) & 1) * 8;
        const int hi8 = l >> 4;
#pragma unroll
        for (int kc = 0; kc < 4; ++kc) {
            const int c = 2 * kc + hi8;
            ldsm4(Qh[kc], smBase + qrow * 128 + ((c ^ (qrow & 7)) << 4));
        }
    }

    float O[8][4];
#pragma unroll
    for (int n = 0; n < 8; ++n)
#pragma unroll
        for (int j = 0; j < 4; ++j) O[n][j] = 0.f;
    float Lacc[4] = {0.f, 0.f, 0.f, 0.f};

    const int r = l & 7;
    const int rS  = (l >> 4) * 8 + r;        // S-tile ldsm row base
    const int cS  = (l >> 3) & 1;            // S-tile ldsm col offset
    const int rV  = ((l >> 3) & 1) * 8 + r;  // V-tile ldsm row base
    const int cV  = l >> 4;                  // V-tile ldsm col offset

    for (int kb = 0; kb < NKT; ++kb) {
        CP_WAIT(1);
        __syncthreads();
        if (kb + 2 < NKT)
            issue_tile(smBase + 16384 + ((kb + 2) % 3) * 16384,
                       kvBase + (kb + 2) * 64, tid);
        CP_COMMIT();

        const uint32_t uKH = smBase + 16384 + (kb % 3) * 16384;
        const uint32_t uVH = uKH + 8192;

        // sd[np&1] ping-pong: S-chunk np computed one step ahead of exp/PV
        float sd[2][2][4];

        // S chunk 0
        {
            const int kk = rS;
#pragma unroll
            for (int j = 0; j < 4; ++j) { sd[0][0][j] = 0.f; sd[0][1][j] = 0.f; }
#pragma unroll
            for (int kc = 0; kc < 4; ++kc) {
                uint32_t kh[4];
                ldsm4(kh, uKH + kk * 128 + (((2 * kc + cS) ^ (kk & 7)) << 4));
                mma16816(sd[0][0], Qh[kc], kh[0], kh[1]);
                mma16816(sd[0][1], Qh[kc], kh[2], kh[3]);
            }
        }

#pragma unroll
        for (int np = 0; np < 4; ++np) {
            const int cur = np & 1, nxt = cur ^ 1;
            // ---- S chunk np+1 (tensor) — issued before exp(np) so HMMA
            //      fills the pipe underneath the MUFU burst ----
            if (np < 3) {
                const int kk = 16 * (np + 1) + rS;
#pragma unroll
                for (int j = 0; j < 4; ++j) { sd[nxt][0][j] = 0.f; sd[nxt][1][j] = 0.f; }
#pragma unroll
                for (int kc = 0; kc < 4; ++kc) {
                    uint32_t kh[4];
                    ldsm4(kh, uKH + kk * 128 + (((2 * kc + cS) ^ (kk & 7)) << 4));
                    mma16816(sd[nxt][0], Qh[kc], kh[0], kh[1]);
                    mma16816(sd[nxt][1], Qh[kc], kh[2], kh[3]);
                }
            }
            // ---- exp chunk np (MUFU/ALU) ----
            uint32_t Ah[4];
            {
                float e0 = ex2f(sd[cur][0][0] * CEXP);
                float e1 = ex2f(sd[cur][0][1] * CEXP);
                float e2 = ex2f(sd[cur][0][2] * CEXP);
                float e3 = ex2f(sd[cur][0][3] * CEXP);
                float e4 = ex2f(sd[cur][1][0] * CEXP);
                float e5 = ex2f(sd[cur][1][1] * CEXP);
                float e6 = ex2f(sd[cur][1][2] * CEXP);
                float e7 = ex2f(sd[cur][1][3] * CEXP);
                Ah[0] = hpack(e0, e1); Ah[1] = hpack(e2, e3);
                Ah[2] = hpack(e4, e5); Ah[3] = hpack(e6, e7);
            }
            // ---- L and PV chunk np (tensor) ----
            mma16816(Lacc, Ah, ONES16, ONES16);
            const int kkv = 16 * np + rV;
#pragma unroll
            for (int npo = 0; npo < 4; ++npo) {
                uint32_t vh[4];
                ldsm4t(vh, uVH + kkv * 128 + (((2 * npo + cV) ^ (kkv & 7)) << 4));
                mma16816(O[2*npo],   Ah, vh[0], vh[1]);
                mma16816(O[2*npo+1], Ah, vh[2], vh[3]);
            }
        }
    }

    {
        const int row0 = qb * QB + w * 16 + (l >> 2);
        const int t    = l & 3;
        float* op = g_Opart[split];
#pragma unroll
        for (int n = 0; n < 8; ++n) {
            *reinterpret_cast<float2*>(op + (size_t)row0 * HD + 8 * n + 2 * t) =
                make_float2(O[n][0], O[n][1]);
            *reinterpret_cast<float2*>(op + (size_t)(row0 + 8) * HD + 8 * n + 2 * t) =
                make_float2(O[n][2], O[n][3]);
        }
        if ((l & 3) == 0) {
            g_lpart[split][row0]     = Lacc[0];
            g_lpart[split][row0 + 8] = Lacc[2];
        }
    }
}

// ---------------------------------------------------------------------------
// Kernel 2: fused combine + output GEMM, fp16 MMA (head hi/lo 2-pass x Wh).
// Grid (64, 4): 128x128 per CTA, 256 threads (8 warps x 16 rows).
// Smem: Hhi@0 (16KB), Hlo@16384, W@32768 (16KB) = 48KB static.
// ---------------------------------------------------------------------------
__global__ __launch_bounds__(256) void out_gemm(float* __restrict__ out) {
    __shared__ __align__(1024) unsigned char sg[49152];
    __shared__ float sInv[128];

    const int tid = threadIdx.x;
    const int w   = tid >> 5;
    const int l   = tid & 31;
    const int mBase = blockIdx.x * 128;
    const int nBase = blockIdx.y * 128;
    const uint32_t sb = smem_u32(sg);

    // ---- stage W tile via cp.async ----
    {
        const int nrow = tid >> 1, sel = tid & 1;
        const __half* src = g_wht + (size_t)(nBase + nrow) * HD;
        const uint32_t dstRow = sb + 32768 + nrow * 128;
#pragma unroll
        for (int i = 0; i < 4; ++i) {
            const int ch = sel * 4 + i;
            CP_ASYNC16(dstRow + ((ch ^ (nrow & 7)) << 4), src + ch * 8);
        }
        CP_COMMIT();
    }

    // ---- load O partials ----
    const int row = tid >> 1, sel = tid & 1;
    float4 a4[8];
    {
        const float4* o0 = reinterpret_cast<const float4*>(
            g_Opart[0] + (size_t)(mBase + row) * HD + sel * 32);
        const float4* o1 = reinterpret_cast<const float4*>(
            g_Opart[1] + (size_t)(mBase + row) * HD + sel * 32);
#pragma unroll
        for (int i = 0; i < 8; ++i) a4[i] = o0[i];
#pragma unroll
        for (int i = 0; i < 8; ++i) {
            float4 b = o1[i];
            a4[i].x += b.x; a4[i].y += b.y; a4[i].z += b.z; a4[i].w += b.w;
        }
    }
    if (tid < 128)
        sInv[tid] = 1.0f / (g_lpart[0][mBase + tid] + g_lpart[1][mBase + tid]);
    __syncthreads();

    // ---- combine, pack hi/lo fp16, store swizzled ----
    {
        const float inv = sInv[row];
        float fv[32];
#pragma unroll
        for (int i = 0; i < 8; ++i) {
            fv[4*i]   = a4[i].x * inv; fv[4*i+1] = a4[i].y * inv;
            fv[4*i+2] = a4[i].z * inv; fv[4*i+3] = a4[i].w * inv;
        }
        const uint32_t rowOff = row * 128;
#pragma unroll
        for (int g = 0; g < 4; ++g) {
            const int ch = sel * 4 + g;
            uint32_t hh[4], ll[4];
#pragma unroll
            for (int p = 0; p < 4; ++p)
                packpair(fv[8*g + 2*p], fv[8*g + 2*p + 1], hh[p], ll[p]);
            const uint32_t swo = ((ch ^ (row & 7)) << 4);
            *reinterpret_cast<uint4*>(sg + (rowOff + swo)) =
                make_uint4(hh[0], hh[1], hh[2], hh[3]);
            *reinterpret_cast<uint4*>(sg + (16384 + rowOff + swo)) =
                make_uint4(ll[0], ll[1], ll[2], ll[3]);
        }
    }
    CP_WAIT(0);
    __syncthreads();

    // ---- fragments & MMA ----
    uint32_t Hh[4][4], Hl[4][4];
    {
        const int hrow = w * 16 + (l & 7) + ((l >> 3) & 1) * 8;
        const int hi8 = l >> 4;
#pragma unroll
        for (int kc = 0; kc < 4; ++kc) {
            const int c = 2 * kc + hi8;
            const uint32_t addr = sb + hrow * 128 + ((c ^ (hrow & 7)) << 4);
            ldsm4(Hh[kc], addr);
            ldsm4(Hl[kc], addr + 16384);
        }
    }

    float oD[16][4];
#pragma unroll
    for (int n = 0; n < 16; ++n)
#pragma unroll
        for (int j = 0; j < 4; ++j) oD[n][j] = 0.f;

    const int r = l & 7;
#pragma unroll
    for (int np = 0; np < 8; ++np) {
#pragma unroll
        for (int kc = 0; kc < 4; ++kc) {
            const int kk = 16 * np + (l >> 4) * 8 + r;
            const int c  = 2 * kc + ((l >> 3) & 1);
            uint32_t b[4];
            ldsm4(b, sb + 32768 + kk * 128 + ((c ^ (kk & 7)) << 4));
            mma16816(oD[2*np],   Hh[kc], b[0], b[1]);
            mma16816(oD[2*np+1], Hh[kc], b[2], b[3]);
            mma16816(oD[2*np],   Hl[kc], b[0], b[1]);
            mma16816(oD[2*np+1], Hl[kc], b[2], b[3]);
        }
    }

    // ---- store ----
    {
        const int row0 = mBase + w * 16 + (l >> 2);
        const int t    = l & 3;
#pragma unroll
        for (int n = 0; n < 16; ++n) {
            const int col = nBase + 8 * n + 2 * t;
            *reinterpret_cast<float2*>(out + (size_t)row0 * WW + col) =
                make_float2(oD[n][0], oD[n][1]);
            *reinterpret_cast<float2*>(out + (size_t)(row0 + 8) * WW + col) =
                make_float2(oD[n][2], oD[n][3]);
        }
    }
}

// ---------------------------------------------------------------------------
extern "C" void kernel_launch(void* const* d_in, const int* in_sizes, int n_in,
                              void* d_out, int out_size) {
    const float* q   = (const float*)d_in[0];
    const float* k   = (const float*)d_in[1];
    const float* v   = (const float*)d_in[2];
    const float* w_o = (const float*)d_in[3];
    float* out = (float*)d_out;

    cudaFuncSetAttribute(attn_mma, cudaFuncAttributeMaxDynamicSharedMemorySize, 65536);

    prologue_kernel<<<384, 256>>>(q, k, v, w_o);
    attn_mma<<<NQB * KSPLIT, 256, 65536>>>(q, k, v);
    out_gemm<<<dim3(S_LEN / 128, WW / 128), 256>>>(out);
}

// round 12
// speedup vs baseline: 2.5054x; 1.0211x over previous
#include <cuda_runtime.h>
#include <cuda_fp16.h>
#include <cstdint>

#define S_LEN 8192
#define HD 64
#define NHEADS 8
#define WW 512
#define QB 128
#define NQB (S_LEN/QB)            /* 64 */
#define UNITS 8192                /* 64 qb x 128 key-tiles */
#define ATTN_GRID 148
#define NSLOT 4
#define CEXP 0.1803368801111204f  /* 0.125 * log2(e) */

static __device__ float g_Opart[NSLOT][S_LEN * HD];   // zero-init; unused slots stay 0
static __device__ float g_lpart[NSLOT][S_LEN];
static __device__ __align__(16) __half g_qh[S_LEN * HD];
static __device__ __align__(16) __half g_kh[S_LEN * HD];
static __device__ __align__(16) __half g_vh[S_LEN * HD];
static __device__ __align__(16) __half g_wht[WW * HD];   // W_sum^T fp16 [n][k]

// ---------------- helpers ----------------
__device__ __forceinline__ uint32_t smem_u32(const void* p) {
    uint32_t a;
    asm("{ .reg .u64 t; cvta.to.shared.u64 t, %1; cvt.u32.u64 %0, t; }" : "=r"(a) : "l"(p));
    return a;
}
__device__ __forceinline__ void ldsm4(uint32_t* r, uint32_t a) {
    asm volatile("ldmatrix.sync.aligned.m8n8.x4.shared.b16 {%0,%1,%2,%3}, [%4];"
                 : "=r"(r[0]), "=r"(r[1]), "=r"(r[2]), "=r"(r[3]) : "r"(a));
}
__device__ __forceinline__ void ldsm4t(uint32_t* r, uint32_t a) {
    asm volatile("ldmatrix.sync.aligned.m8n8.x4.trans.shared.b16 {%0,%1,%2,%3}, [%4];"
                 : "=r"(r[0]), "=r"(r[1]), "=r"(r[2]), "=r"(r[3]) : "r"(a));
}
__device__ __forceinline__ void mma16816(float* d, const uint32_t* a, uint32_t b0, uint32_t b1) {
    asm volatile(
        "mma.sync.aligned.m16n8k16.row.col.f32.f16.f16.f32 "
        "{%0,%1,%2,%3}, {%4,%5,%6,%7}, {%8,%9}, {%0,%1,%2,%3};"
        : "+f"(d[0]), "+f"(d[1]), "+f"(d[2]), "+f"(d[3])
        : "r"(a[0]), "r"(a[1]), "r"(a[2]), "r"(a[3]), "r"(b0), "r"(b1));
}
__device__ __forceinline__ uint32_t hpack(float a, float b) {
    __half2 h = __floats2half2_rn(a, b);
    return *reinterpret_cast<uint32_t*>(&h);
}
__device__ __forceinline__ void packpair(float a, float b, uint32_t& hi, uint32_t& lo) {
    __half2 h = __floats2half2_rn(a, b);
    hi = *reinterpret_cast<uint32_t*>(&h);
    float fa = __half2float(h.x);
    float fb = __half2float(h.y);
    lo = hpack(a - fa, b - fb);
}
__device__ __forceinline__ float ex2f(float x) {
    float y; asm("ex2.approx.f32 %0, %1;" : "=f"(y) : "f"(x)); return y;
}
#define CP_ASYNC16(dst, src) \
    asm volatile("cp.async.cg.shared.global [%0], [%1], 16;" :: "r"(dst), "l"(src))
#define CP_COMMIT() asm volatile("cp.async.commit_group;" ::: "memory")
#define CP_WAIT(n)  asm volatile("cp.async.wait_group %0;" :: "n"(n) : "memory")

// first CTA whose range contains unit u (u0(c) = floor(c*UNITS/ATTN_GRID))
__device__ __forceinline__ int cta_of_unit(int u) {
    return (u * ATTN_GRID + ATTN_GRID - 1) / UNITS;
}

// ---------------------------------------------------------------------------
// Kernel 0 (merged prologue): blocks 0..1535 convert q/k/v (4 elems/thread);
// blocks 1536..1663 reduce w_o -> fp16 transposed W_sum.
// ---------------------------------------------------------------------------
__global__ void prologue_kernel(const float* __restrict__ q, const float* __restrict__ k,
                                const float* __restrict__ v, const float* __restrict__ w_o) {
    if (blockIdx.x < 1536) {
        const int a = blockIdx.x >> 9;                         // tensor 0..2
        const int idx = ((blockIdx.x & 511) << 8) + threadIdx.x;  // 0..131071 float4s
        const float* srcs[3] = {q, k, v};
        __half* dsts[3] = {g_qh, g_kh, g_vh};
        float4 x = reinterpret_cast<const float4*>(srcs[a])[idx];
        reinterpret_cast<uint2*>(dsts[a])[idx] =
            make_uint2(hpack(x.x, x.y), hpack(x.z, x.w));
    } else {
        int idx = (blockIdx.x - 1536) * blockDim.x + threadIdx.x;   // 0..32767
        int d = idx >> 9;
        int c = idx & 511;
        float s = 0.f;
#pragma unroll
        for (int h = 0; h < NHEADS; ++h)
            s += w_o[(h * HD + d) * WW + c];
        g_wht[c * HD + d] = __float2half(s);
    }
}

// ---------------------------------------------------------------------------
// Kernel 1: persistent flash attention over flat (qb, ktile) units.
// 148 CTAs x 256 threads (8 warps x 16 rows). cp.async triple-buffered KH/VH.
// Smem: Q@0 (16KB); buf b @ 16384 + b*16384: KH@0 VH@8192. Total 64KB.
// ---------------------------------------------------------------------------
__device__ __forceinline__ void issue_tile(uint32_t bufBase, int keyRow0, int tid) {
    const int key = tid >> 2, sub = tid & 3;
    const size_t gOff = (size_t)(keyRow0 + key) * HD;
#pragma unroll
    for (int i = 0; i < 2; ++i) {
        const int ch = sub * 2 + i;
        const uint32_t swo = ((ch ^ (key & 7)) << 4);
        CP_ASYNC16(bufBase + key * 128 + swo, g_kh + gOff + ch * 8);
        CP_ASYNC16(bufBase + 8192 + key * 128 + swo, g_vh + gOff + ch * 8);
    }
}

__global__ __launch_bounds__(256, 1)
void attn_mma() {
    extern __shared__ __align__(1024) unsigned char sm[];
    const int tid = threadIdx.x;
    const int w   = tid >> 5;
    const int l   = tid & 31;
    const int c   = blockIdx.x;
    const uint32_t smBase = smem_u32(sm);

    const int u0 = (c * UNITS) / ATTN_GRID;
    const int u1 = ((c + 1) * UNITS) / ATTN_GRID;
    const int n  = u1 - u0;

    const int r = l & 7;
    const int rS = (l >> 4) * 8 + r;
    const int cS = (l >> 3) & 1;
    const int rV = ((l >> 3) & 1) * 8 + r;
    const int cV = l >> 4;
    const int qrow = w * 16 + (l & 7) + ((l >> 3) & 1) * 8;
    const int hi8  = l >> 4;

    // ---- Q loader (LDG + STS, CTA-wide) ----
    const int qldRow = tid >> 1, qldSel = tid & 1;
    auto load_q = [&](int qb) {
        const size_t gOff = (size_t)(qb * QB + qldRow) * HD;
        char* dstRow = (char*)sm + qldRow * 128;
#pragma unroll
        for (int i = 0; i < 4; ++i) {
            const int ch = qldSel * 4 + i;
            uint4 val = *reinterpret_cast<const uint4*>(g_qh + gOff + ch * 8);
            *reinterpret_cast<uint4*>(dstRow + ((ch ^ (qldRow & 7)) << 4)) = val;
        }
    };

    uint32_t Qh[4][4];
    auto frag_q = [&]() {
#pragma unroll
        for (int kc = 0; kc < 4; ++kc) {
            const int cc = 2 * kc + hi8;
            ldsm4(Qh[kc], smBase + qrow * 128 + ((cc ^ (qrow & 7)) << 4));
        }
    };

    float O[8][4];
    float lacc0, lacc1;
    auto reset_acc = [&]() {
#pragma unroll
        for (int nn = 0; nn < 8; ++nn)
#pragma unroll
            for (int j = 0; j < 4; ++j) O[nn][j] = 0.f;
        lacc0 = 0.f; lacc1 = 0.f;
    };

    auto write_partial = [&](int qb, int slot) {
        const int row0 = qb * QB + w * 16 + (l >> 2);
        const int t    = l & 3;
        float* op = g_Opart[slot];
#pragma unroll
        for (int nn = 0; nn < 8; ++nn) {
            *reinterpret_cast<float2*>(op + (size_t)row0 * HD + 8 * nn + 2 * t) =
                make_float2(O[nn][0], O[nn][1]);
            *reinterpret_cast<float2*>(op + (size_t)(row0 + 8) * HD + 8 * nn + 2 * t) =
                make_float2(O[nn][2], O[nn][3]);
        }
        float s0 = lacc0, s1 = lacc1;
        s0 += __shfl_xor_sync(0xffffffffu, s0, 1);
        s0 += __shfl_xor_sync(0xffffffffu, s0, 2);
        s1 += __shfl_xor_sync(0xffffffffu, s1, 1);
        s1 += __shfl_xor_sync(0xffffffffu, s1, 2);
        if ((l & 3) == 0) {
            g_lpart[slot][row0]     = s0;
            g_lpart[slot][row0 + 8] = s1;
        }
    };

    // ---- prologue ----
    int cur_qb = u0 >> 7;
    load_q(cur_qb);
    issue_tile(smBase + 16384, (u0 & 127) * 64, tid);               CP_COMMIT();
    issue_tile(smBase + 32768, ((u0 + 1) & 127) * 64, tid);         CP_COMMIT();
    __syncthreads();
    frag_q();
    reset_acc();

    for (int u = u0; u < u1; ++u) {
        const int i = u - u0;
        CP_WAIT(1);
        __syncthreads();    // all warps done with buf (i+2)%3 and previous tile

        const int q_of_u = u >> 7;
        if (q_of_u != cur_qb) {
            const int slot = c - cta_of_unit(cur_qb << 7);
            write_partial(cur_qb, slot);
            cur_qb = q_of_u;
            load_q(cur_qb);
            __syncthreads();
            frag_q();
            reset_acc();
        }

        if (i + 2 < n)
            issue_tile(smBase + 16384 + ((i + 2) % 3) * 16384,
                       ((u + 2) & 127) * 64, tid);
        CP_COMMIT();

        const uint32_t uKH = smBase + 16384 + (i % 3) * 16384;
        const uint32_t uVH = uKH + 8192;

        float sd[2][2][4];
        // S chunk 0
        {
            const int kk = rS;
#pragma unroll
            for (int j = 0; j < 4; ++j) { sd[0][0][j] = 0.f; sd[0][1][j] = 0.f; }
#pragma unroll
            for (int kc = 0; kc < 4; ++kc) {
                uint32_t kh[4];
                ldsm4(kh, uKH + kk * 128 + (((2 * kc + cS) ^ (kk & 7)) << 4));
                mma16816(sd[0][0], Qh[kc], kh[0], kh[1]);
                mma16816(sd[0][1], Qh[kc], kh[2], kh[3]);
            }
        }

#pragma unroll
        for (int np = 0; np < 4; ++np) {
            const int cur = np & 1, nxt = cur ^ 1;
            if (np < 3) {
                const int kk = 16 * (np + 1) + rS;
#pragma unroll
                for (int j = 0; j < 4; ++j) { sd[nxt][0][j] = 0.f; sd[nxt][1][j] = 0.f; }
#pragma unroll
                for (int kc = 0; kc < 4; ++kc) {
                    uint32_t kh[4];
                    ldsm4(kh, uKH + kk * 128 + (((2 * kc + cS) ^ (kk & 7)) << 4));
                    mma16816(sd[nxt][0], Qh[kc], kh[0], kh[1]);
                    mma16816(sd[nxt][1], Qh[kc], kh[2], kh[3]);
                }
            }
            // exp + l accumulation (FMA/MUFU pipes; tensor stays busy)
            uint32_t Ah[4];
            {
                float e0 = ex2f(sd[cur][0][0] * CEXP);
                float e1 = ex2f(sd[cur][0][1] * CEXP);
                float e2 = ex2f(sd[cur][0][2] * CEXP);
                float e3 = ex2f(sd[cur][0][3] * CEXP);
                float e4 = ex2f(sd[cur][1][0] * CEXP);
                float e5 = ex2f(sd[cur][1][1] * CEXP);
                float e6 = ex2f(sd[cur][1][2] * CEXP);
                float e7 = ex2f(sd[cur][1][3] * CEXP);
                lacc0 += (e0 + e1) + (e4 + e5);
                lacc1 += (e2 + e3) + (e6 + e7);
                Ah[0] = hpack(e0, e1); Ah[1] = hpack(e2, e3);
                Ah[2] = hpack(e4, e5); Ah[3] = hpack(e6, e7);
            }
            // PV chunk np
            const int kkv = 16 * np + rV;
#pragma unroll
            for (int npo = 0; npo < 4; ++npo) {
                uint32_t vh[4];
                ldsm4t(vh, uVH + kkv * 128 + (((2 * npo + cV) ^ (kkv & 7)) << 4));
                mma16816(O[2*npo],   Ah, vh[0], vh[1]);
                mma16816(O[2*npo+1], Ah, vh[2], vh[3]);
            }
        }
    }

    {
        const int slot = c - cta_of_unit(cur_qb << 7);
        write_partial(cur_qb, slot);
    }
}

// ---------------------------------------------------------------------------
// Kernel 2: fused combine (4 slots) + output GEMM, fp16 MMA (hi/lo 2-pass).
// Grid (64, 4): 128x128 per CTA, 256 threads (8 warps x 16 rows).
// Smem: Hhi@0 (16KB), Hlo@16384, W@32768 (16KB) = 48KB static.
// ---------------------------------------------------------------------------
__global__ __launch_bounds__(256) void out_gemm(float* __restrict__ out) {
    __shared__ __align__(1024) unsigned char sg[49152];
    __shared__ float sInv[128];

    const int tid = threadIdx.x;
    const int w   = tid >> 5;
    const int l   = tid & 31;
    const int mBase = blockIdx.x * 128;
    const int nBase = blockIdx.y * 128;
    const uint32_t sb = smem_u32(sg);

    // ---- stage W tile via cp.async ----
    {
        const int nrow = tid >> 1, sel = tid & 1;
        const __half* src = g_wht + (size_t)(nBase + nrow) * HD;
        const uint32_t dstRow = sb + 32768 + nrow * 128;
#pragma unroll
        for (int i = 0; i < 4; ++i) {
            const int ch = sel * 4 + i;
            CP_ASYNC16(dstRow + ((ch ^ (nrow & 7)) << 4), src + ch * 8);
        }
        CP_COMMIT();
    }

    // ---- load & sum O partial slots ----
    const int row = tid >> 1, sel = tid & 1;
    float4 a4[8];
    {
        const size_t off = (size_t)(mBase + row) * HD + sel * 32;
#pragma unroll
        for (int i = 0; i < 8; ++i)
            a4[i] = reinterpret_cast<const float4*>(g_Opart[0] + off)[i];
#pragma unroll
        for (int s = 1; s < NSLOT; ++s) {
            const float4* os = reinterpret_cast<const float4*>(g_Opart[s] + off);
#pragma unroll
            for (int i = 0; i < 8; ++i) {
                float4 b = os[i];
                a4[i].x += b.x; a4[i].y += b.y; a4[i].z += b.z; a4[i].w += b.w;
            }
        }
    }
    if (tid < 128) {
        float ls = 0.f;
#pragma unroll
        for (int s = 0; s < NSLOT; ++s) ls += g_lpart[s][mBase + tid];
        sInv[tid] = 1.0f / ls;
    }
    __syncthreads();

    // ---- combine, pack hi/lo fp16, store swizzled ----
    {
        const float inv = sInv[row];
        float fv[32];
#pragma unroll
        for (int i = 0; i < 8; ++i) {
            fv[4*i]   = a4[i].x * inv; fv[4*i+1] = a4[i].y * inv;
            fv[4*i+2] = a4[i].z * inv; fv[4*i+3] = a4[i].w * inv;
        }
        const uint32_t rowOff = row * 128;
#pragma unroll
        for (int g = 0; g < 4; ++g) {
            const int ch = sel * 4 + g;
            uint32_t hh[4], ll[4];
#pragma unroll
            for (int p = 0; p < 4; ++p)
                packpair(fv[8*g + 2*p], fv[8*g + 2*p + 1], hh[p], ll[p]);
            const uint32_t swo = ((ch ^ (row & 7)) << 4);
            *reinterpret_cast<uint4*>(sg + (rowOff + swo)) =
                make_uint4(hh[0], hh[1], hh[2], hh[3]);
            *reinterpret_cast<uint4*>(sg + (16384 + rowOff + swo)) =
                make_uint4(ll[0], ll[1], ll[2], ll[3]);
        }
    }
    CP_WAIT(0);
    __syncthreads();

    uint32_t Hh[4][4], Hl[4][4];
    {
        const int hrow = w * 16 + (l & 7) + ((l >> 3) & 1) * 8;
        const int hi8 = l >> 4;
#pragma unroll
        for (int kc = 0; kc < 4; ++kc) {
            const int cc = 2 * kc + hi8;
            const uint32_t addr = sb + hrow * 128 + ((cc ^ (hrow & 7)) << 4);
            ldsm4(Hh[kc], addr);
            ldsm4(Hl[kc], addr + 16384);
        }
    }

    float oD[16][4];
#pragma unroll
    for (int nn = 0; nn < 16; ++nn)
#pragma unroll
        for (int j = 0; j < 4; ++j) oD[nn][j] = 0.f;

    const int r = l & 7;
#pragma unroll
    for (int np = 0; np < 8; ++np) {
#pragma unroll
        for (int kc = 0; kc < 4; ++kc) {
            const int kk = 16 * np + (l >> 4) * 8 + r;
            const int cc = 2 * kc + ((l >> 3) & 1);
            uint32_t b[4];
            ldsm4(b, sb + 32768 + kk * 128 + ((cc ^ (kk & 7)) << 4));
            mma16816(oD[2*np],   Hh[kc], b[0], b[1]);
            mma16816(oD[2*np+1], Hh[kc], b[2], b[3]);
            mma16816(oD[2*np],   Hl[kc], b[0], b[1]);
            mma16816(oD[2*np+1], Hl[kc], b[2], b[3]);
        }
    }

    {
        const int row0 = mBase + w * 16 + (l >> 2);
        const int t    = l & 3;
#pragma unroll
        for (int nn = 0; nn < 16; ++nn) {
            const int col = nBase + 8 * nn + 2 * t;
            *reinterpret_cast<float2*>(out + (size_t)row0 * WW + col) =
                make_float2(oD[nn][0], oD[nn][1]);
            *reinterpret_cast<float2*>(out + (size_t)(row0 + 8) * WW + col) =
                make_float2(oD[nn][2], oD[nn][3]);
        }
    }
}

// ---------------------------------------------------------------------------
extern "C" void kernel_launch(void* const* d_in, const int* in_sizes, int n_in,
                              void* d_out, int out_size) {
    const float* q   = (const float*)d_in[0];
    const float* k   = (const float*)d_in[1];
    const float* v   = (const float*)d_in[2];
    const float* w_o = (const float*)d_in[3];
    float* out = (float*)d_out;

    cudaFuncSetAttribute(attn_mma, cudaFuncAttributeMaxDynamicSharedMemorySize, 65536);

    prologue_kernel<<<1664, 256>>>(q, k, v, w_o);
    attn_mma<<<ATTN_GRID, 256, 65536>>>();
    out_gemm<<<dim3(S_LEN / 128, WW / 128), 256>>>(out);
}